// round 1
// baseline (speedup 1.0000x reference)
#include <cuda_runtime.h>
#include <cuda_bf16.h>
#include <math.h>

#define NN 48758
#define EE 750000
#define D 128
#define RELS 5

// ---------------- static device scratch (no allocation allowed) ----------------
__device__ float g_buf0[NN * D];
__device__ float g_buf1[NN * D];
__device__ float g_xlin[NN * D];
__device__ float g_y[(size_t)RELS * NN * D];
__device__ float g_z[NN * D];
__device__ float g_bnsum[D];
__device__ float g_bnssum[D];
__device__ int   g_srccnt[NN];
__device__ int   g_dstcnt[NN];
__device__ float g_dis[NN];
__device__ int   g_rowoff[NN + 1];
__device__ int   g_cursor[NN];
__device__ int   g_pack[EE];
__device__ float g_norm[EE];

// ---------------- zero init ----------------
__global__ void zero_kernel() {
    int i = blockIdx.x * blockDim.x + threadIdx.x;
    if (i < NN) { g_srccnt[i] = 0; g_dstcnt[i] = 0; }
    if (i < D)  { g_bnsum[i] = 0.f; g_bnssum[i] = 0.f; }
}

// ---------------- GEMM: C[M,128] = A[M,128] @ B[128,128] (+bias), batched over z ----------------
// 128x128 block tile, 256 threads, 8x8 micro-tile per thread. B staged in smem (64KB dyn).
__global__ __launch_bounds__(256, 2) void gemm_nt(
    const float* __restrict__ A, const float* __restrict__ B,
    const float* __restrict__ bias, float* __restrict__ C,
    int M, int strideB, long long strideC)
{
    extern __shared__ float Bs[];  // [128][128]
    const float* Bb = B + (size_t)blockIdx.z * (size_t)strideB;
    float* Cb = C + (size_t)blockIdx.z * (size_t)strideC;

    // stage B (16384 floats) via float4
    for (int i = threadIdx.x; i < D * D / 4; i += 256)
        ((float4*)Bs)[i] = ((const float4*)Bb)[i];
    __syncthreads();

    const int tx = threadIdx.x & 15;      // 16 col-threads * 8 cols = 128
    const int ty = threadIdx.x >> 4;      // 16 row-threads * 8 rows = 128
    const int rowBase = blockIdx.x * 128 + ty * 8;

    const float* arow[8];
#pragma unroll
    for (int i = 0; i < 8; i++) {
        int r = rowBase + i;
        if (r >= M) r = M - 1;             // clamp (stores guarded later)
        arow[i] = A + (size_t)r * D;
    }

    float acc[8][8];
#pragma unroll
    for (int i = 0; i < 8; i++)
#pragma unroll
        for (int j = 0; j < 8; j++) acc[i][j] = 0.f;

#pragma unroll 2
    for (int k = 0; k < D; k += 4) {
        float4 a4[8];
#pragma unroll
        for (int i = 0; i < 8; i++) a4[i] = *(const float4*)(arow[i] + k);
#pragma unroll
        for (int kk = 0; kk < 4; kk++) {
            float4 b0 = *(const float4*)&Bs[(k + kk) * D + tx * 8];
            float4 b1 = *(const float4*)&Bs[(k + kk) * D + tx * 8 + 4];
            float b[8] = { b0.x, b0.y, b0.z, b0.w, b1.x, b1.y, b1.z, b1.w };
#pragma unroll
            for (int i = 0; i < 8; i++) {
                float av = ((const float*)&a4[i])[kk];
#pragma unroll
                for (int j = 0; j < 8; j++) acc[i][j] = fmaf(av, b[j], acc[i][j]);
            }
        }
    }

    float bb[8];
#pragma unroll
    for (int j = 0; j < 8; j++) bb[j] = bias ? bias[tx * 8 + j] : 0.f;

#pragma unroll
    for (int i = 0; i < 8; i++) {
        int r = rowBase + i;
        if (r < M) {
            float4 v0 = { acc[i][0] + bb[0], acc[i][1] + bb[1], acc[i][2] + bb[2], acc[i][3] + bb[3] };
            float4 v1 = { acc[i][4] + bb[4], acc[i][5] + bb[5], acc[i][6] + bb[6], acc[i][7] + bb[7] };
            *(float4*)&Cb[(size_t)r * D + tx * 8]     = v0;
            *(float4*)&Cb[(size_t)r * D + tx * 8 + 4] = v1;
        }
    }
}

// ---------------- BatchNorm (training-mode batch stats) ----------------
__global__ void bn_stats(const float* __restrict__ h) {
    int c = threadIdx.x;                   // 128 threads
    float s = 0.f, ss = 0.f;
    for (int r = blockIdx.x; r < NN; r += gridDim.x) {
        float v = h[(size_t)r * D + c];
        s += v; ss += v * v;
    }
    atomicAdd(&g_bnsum[c], s);
    atomicAdd(&g_bnssum[c], ss);
}

__global__ void bn_apply(const float* __restrict__ in, float* __restrict__ out,
                         const float* __restrict__ g, const float* __restrict__ b) {
    int i = blockIdx.x * blockDim.x + threadIdx.x;
    if (i >= NN * D) return;
    int c = i & (D - 1);
    float mu = g_bnsum[c] * (1.f / NN);
    float var = g_bnssum[c] * (1.f / NN) - mu * mu;
    float v = (in[i] - mu) * rsqrtf(var + 1e-5f) * g[c] + b[c];
    out[i] = fmaxf(v, 0.f);
}

// ---------------- graph preprocessing ----------------
__global__ void count_edges(const int* __restrict__ ei, int E) {
    int e = blockIdx.x * blockDim.x + threadIdx.x;
    if (e >= E) return;
    atomicAdd(&g_dstcnt[ei[e]], 1);        // row 0 = dst
    atomicAdd(&g_srccnt[ei[E + e]], 1);    // row 1 = src  (deg over col in reference)
}

__global__ void dis_kernel() {
    int i = blockIdx.x * blockDim.x + threadIdx.x;
    if (i >= NN) return;
    int d = g_srccnt[i];
    g_dis[i] = (d > 0) ? rsqrtf((float)d) : 0.f;
}

__global__ void scan_kernel() {            // 1 block, 1024 threads; exclusive scan of dst counts
    __shared__ int sh[1024];
    int tid = threadIdx.x;
    int carry = 0;
    for (int base = 0; base < NN; base += 1024) {
        int i = base + tid;
        int v = (i < NN) ? g_dstcnt[i] : 0;
        sh[tid] = v;
        __syncthreads();
        for (int o = 1; o < 1024; o <<= 1) {
            int x = (tid >= o) ? sh[tid - o] : 0;
            __syncthreads();
            sh[tid] += x;
            __syncthreads();
        }
        int incl = sh[tid];
        if (i < NN) {
            int ex = carry + incl - v;
            g_rowoff[i] = ex;
            g_cursor[i] = ex;
        }
        int tot = sh[1023];
        __syncthreads();
        carry += tot;
    }
    if (tid == 0) g_rowoff[NN] = carry;
}

__global__ void scatter_kernel(const int* __restrict__ ei, const int* __restrict__ ety, int E) {
    int e = blockIdx.x * blockDim.x + threadIdx.x;
    if (e >= E) return;
    int dst = ei[e];
    int src = ei[E + e];
    int r = ety[e];
    int pos = atomicAdd(&g_cursor[dst], 1);
    g_pack[pos] = src | (r << 16);                 // src < 65536, r < 8
    g_norm[pos] = g_dis[dst] * g_dis[src];
}

// ---------------- edge aggregation: warp per dst node ----------------
// Fused: gcn-sum + scatter-softmax (no max-shift; |res| is small so exp is safe & exact)
__global__ __launch_bounds__(256) void aggregate(
    const float* __restrict__ xlin, const float* __restrict__ y, float* __restrict__ z)
{
    int w = (blockIdx.x * blockDim.x + threadIdx.x) >> 5;
    int lane = threadIdx.x & 31;
    if (w >= NN) return;
    int beg = g_rowoff[w], end = g_rowoff[w + 1];

    float4 gz = {0.f, 0.f, 0.f, 0.f};
    float4 sz = {0.f, 0.f, 0.f, 0.f};
    float4 tz = {0.f, 0.f, 0.f, 0.f};

    for (int e = beg; e < end; e++) {
        int pk = g_pack[e];
        float nm = g_norm[e];
        int src = pk & 0xFFFF;
        int r = pk >> 16;
        float4 xv = *(const float4*)(xlin + (size_t)src * D + lane * 4);
        float4 rv = *(const float4*)(y + ((size_t)r * NN + (size_t)src) * D + lane * 4);
        gz.x = fmaf(xv.x, nm, gz.x); gz.y = fmaf(xv.y, nm, gz.y);
        gz.z = fmaf(xv.z, nm, gz.z); gz.w = fmaf(xv.w, nm, gz.w);
        float e0 = __expf(rv.x), e1 = __expf(rv.y), e2 = __expf(rv.z), e3 = __expf(rv.w);
        sz.x += e0; sz.y += e1; sz.z += e2; sz.w += e3;
        tz.x = fmaf(rv.x, e0, tz.x); tz.y = fmaf(rv.y, e1, tz.y);
        tz.z = fmaf(rv.z, e2, tz.z); tz.w = fmaf(rv.w, e3, tz.w);
    }

    float4 o;
    if (end > beg) {
        float m0 = tz.x / sz.x, m1 = tz.y / sz.y, m2 = tz.z / sz.z, m3 = tz.w / sz.w;
        o.x = gz.x + 0.1f * fmaxf(m0, 0.f);
        o.y = gz.y + 0.1f * fmaxf(m1, 0.f);
        o.z = gz.z + 0.1f * fmaxf(m2, 0.f);
        o.w = gz.w + 0.1f * fmaxf(m3, 0.f);
    } else {
        o = gz;  // zeros
    }
    *(float4*)(z + (size_t)w * D + lane * 4) = o;
}

// ---------------- final gather + exact GELU ----------------
__global__ void gather_gelu(const float* __restrict__ h, const int* __restrict__ idx,
                            float* __restrict__ out, int NI) {
    int i = blockIdx.x * blockDim.x + threadIdx.x;
    if (i >= NI * D) return;
    int row = idx[i >> 7];
    float v = h[(size_t)row * D + (i & (D - 1))];
    out[i] = 0.5f * v * (1.0f + erff(v * 0.70710678118654752f));
}

// ---------------- launch ----------------
extern "C" void kernel_launch(void* const* d_in, const int* in_sizes, int n_in,
                              void* d_out, int out_size) {
    const float* x      = (const float*)d_in[0];
    const int*   ei     = (const int*)d_in[1];
    const int*   ety    = (const int*)d_in[2];
    /* d_in[3] edge_weight unused by reference */
    const int*   idx    = (const int*)d_in[4];
    const float* proj_w = (const float*)d_in[5];
    const float* proj_b = (const float*)d_in[6];
    const float* bn_g   = (const float*)d_in[7];
    const float* bn_b   = (const float*)d_in[8];
    const float* win_w[2]  = { (const float*)d_in[9],  (const float*)d_in[14] };
    const float* win_b[2]  = { (const float*)d_in[10], (const float*)d_in[15] };
    const float* wrel[2]   = { (const float*)d_in[11], (const float*)d_in[16] };
    const float* cout_w[2] = { (const float*)d_in[12], (const float*)d_in[17] };
    const float* cout_b[2] = { (const float*)d_in[13], (const float*)d_in[18] };

    const int E  = in_sizes[1] / 2;
    const int NI = in_sizes[4];
    float* out = (float*)d_out;

    float *buf0, *buf1, *xlin, *y, *z;
    cudaGetSymbolAddress((void**)&buf0, g_buf0);
    cudaGetSymbolAddress((void**)&buf1, g_buf1);
    cudaGetSymbolAddress((void**)&xlin, g_xlin);
    cudaGetSymbolAddress((void**)&y,    g_y);
    cudaGetSymbolAddress((void**)&z,    g_z);

    cudaFuncSetAttribute(gemm_nt, cudaFuncAttributeMaxDynamicSharedMemorySize, 65536);

    const int GB = (NN + 127) / 128;

    zero_kernel<<<(NN + 255) / 256, 256>>>();

    // input projection -> BN (batch stats) -> relu
    gemm_nt<<<dim3(GB, 1, 1), 256, 65536>>>(x, proj_w, proj_b, buf0, NN, 0, 0);
    bn_stats<<<256, 128>>>(buf0);
    bn_apply<<<(NN * D + 255) / 256, 256>>>(buf0, buf1, bn_g, bn_b);

    // graph preprocessing (CSR by dst + gcn norm)
    count_edges<<<(E + 511) / 512, 512>>>(ei, E);
    dis_kernel<<<(NN + 255) / 256, 256>>>();
    scan_kernel<<<1, 1024>>>();
    scatter_kernel<<<(E + 511) / 512, 512>>>(ei, ety, E);

    const float* hin = buf1;
    float* hout = buf0;
    for (int L = 0; L < 2; L++) {
        gemm_nt<<<dim3(GB, 1, 1), 256, 65536>>>(hin, win_w[L], win_b[L], xlin, NN, 0, 0);
        gemm_nt<<<dim3(GB, 1, RELS), 256, 65536>>>(xlin, wrel[L], nullptr, y, NN, D * D, (long long)NN * D);
        aggregate<<<(NN * 32 + 255) / 256, 256>>>(xlin, y, z);
        gemm_nt<<<dim3(GB, 1, 1), 256, 65536>>>(z, cout_w[L], cout_b[L], hout, NN, 0, 0);
        float* t = (float*)hin; hin = hout; hout = t;
    }

    gather_gelu<<<(NI * D + 255) / 256, 256>>>(hin, idx, out, NI);
}

// round 3
// speedup vs baseline: 1.1505x; 1.1505x over previous
#include <cuda_runtime.h>
#include <cuda_bf16.h>
#include <math.h>
#include <stdint.h>

#define NN 48758
#define EE 750000
#define D 128
#define RELS 5
#define NMAT 15
#define PADK 136                 // padded row length (elements) -> 272B stride, conflict-free ldmatrix
#define WBYTES 69632             // per-matrix prepped weight bytes (hi 34816 + lo 34816)

// ---------------- static device scratch ----------------
__device__ float g_buf0[NN * D];
__device__ float g_buf1[NN * D];
__device__ float g_xlin[NN * D];
__device__ float g_y[(size_t)RELS * NN * D];
__device__ float g_z[NN * D];
__device__ float g_bnsum[D];
__device__ float g_bnssum[D];
__device__ int   g_srccnt[NN];
__device__ int   g_dstcnt[NN];
__device__ float g_dis[NN];
__device__ int   g_rowoff[NN + 1];
__device__ int   g_cursor[NN];
__device__ int   g_pack[EE];
__device__ float g_norm[EE];
__device__ unsigned char g_w[(size_t)NMAT * WBYTES];

// ---------------- helpers ----------------
__device__ __forceinline__ uint32_t smem_u32(const void* p) {
    uint32_t a;
    asm("{ .reg .u64 t; cvta.to.shared.u64 t, %1; cvt.u32.u64 %0, t; }" : "=r"(a) : "l"(p));
    return a;
}
__device__ __forceinline__ uint32_t pack_bf2(__nv_bfloat16 lo, __nv_bfloat16 hi) {
    return ((uint32_t)__bfloat16_as_ushort(hi) << 16) | (uint32_t)__bfloat16_as_ushort(lo);
}
__device__ __forceinline__ void split_pair(float x0, float x1, uint32_t& hi2, uint32_t& lo2) {
    __nv_bfloat16 h0 = __float2bfloat16(x0), h1 = __float2bfloat16(x1);
    __nv_bfloat16 l0 = __float2bfloat16(x0 - __bfloat162float(h0));
    __nv_bfloat16 l1 = __float2bfloat16(x1 - __bfloat162float(h1));
    hi2 = pack_bf2(h0, h1);
    lo2 = pack_bf2(l0, l1);
}
__device__ __forceinline__ void ldmx4(uint32_t* r, uint32_t addr) {
    asm volatile("ldmatrix.sync.aligned.m8n8.x4.shared.b16 {%0,%1,%2,%3}, [%4];"
                 : "=r"(r[0]), "=r"(r[1]), "=r"(r[2]), "=r"(r[3]) : "r"(addr));
}
__device__ __forceinline__ void ldmx4t(uint32_t* r, uint32_t addr) {
    asm volatile("ldmatrix.sync.aligned.m8n8.x4.trans.shared.b16 {%0,%1,%2,%3}, [%4];"
                 : "=r"(r[0]), "=r"(r[1]), "=r"(r[2]), "=r"(r[3]) : "r"(addr));
}
__device__ __forceinline__ void mma16816(float* c, const uint32_t* a, const uint32_t* b) {
    asm volatile(
        "mma.sync.aligned.m16n8k16.row.col.f32.bf16.bf16.f32 "
        "{%0,%1,%2,%3}, {%4,%5,%6,%7}, {%8,%9}, {%0,%1,%2,%3};"
        : "+f"(c[0]), "+f"(c[1]), "+f"(c[2]), "+f"(c[3])
        : "r"(a[0]), "r"(a[1]), "r"(a[2]), "r"(a[3]), "r"(b[0]), "r"(b[1]));
}

// ---------------- weight prep: f32 [K=128,N=128] -> split hi/lo bf16, padded rows ----------------
__global__ void prep_w(const float* __restrict__ src, int matbase) {
    int m = blockIdx.x;
    const float* W = src + (size_t)m * 16384;
    unsigned char* dst = g_w + (size_t)(matbase + m) * WBYTES;
    for (int idx = threadIdx.x; idx < 128 * 64; idx += blockDim.x) {
        int k = idx >> 6, n = (idx & 63) * 2;
        uint32_t hi2, lo2;
        split_pair(W[k * 128 + n], W[k * 128 + n + 1], hi2, lo2);
        *(uint32_t*)(dst + (size_t)(k * PADK + n) * 2) = hi2;
        *(uint32_t*)(dst + 34816 + (size_t)(k * PADK + n) * 2) = lo2;
    }
}

// ---------------- HMMA GEMM: C[M,128] = A[M,128] @ W (+bias), split-bf16 3-term ----------------
// SMEM: A_hi | A_lo | B_hi | B_lo (each 128*136*2 = 34816B) | bias 512B
#define SM_AHI  0
#define SM_ALO  34816
#define SM_BHI  69632
#define SM_BLO  104448
#define SM_BIAS 139264
#define SM_TOTAL 139776

__global__ __launch_bounds__(256, 1) void gemm_mma(
    const float* __restrict__ A, const unsigned char* __restrict__ Wp,
    const float* __restrict__ bias, float* __restrict__ C,
    int M, long long cstride)
{
    extern __shared__ char smem[];
    const unsigned char* Wb = Wp + (size_t)blockIdx.z * WBYTES;
    float* Cb = C + (size_t)blockIdx.z * cstride;
    int tid = threadIdx.x, wid = tid >> 5, lane = tid & 31;
    int rowBase = blockIdx.x * 128;

    // stage B hi+lo (69632 B contiguous) via float4
    for (int i = tid; i < WBYTES / 16; i += 256)
        ((float4*)(smem + SM_BHI))[i] = ((const float4*)Wb)[i];

    if (tid < 128) ((float*)(smem + SM_BIAS))[tid] = bias ? bias[tid] : 0.f;

    // stage A: load f32 rows, split hi/lo bf16
    for (int idx = tid; idx < 128 * 64; idx += 256) {
        int row = idx >> 6, k = (idx & 63) * 2;
        int gr = rowBase + row; if (gr >= M) gr = M - 1;
        float2 a = *(const float2*)(A + (size_t)gr * D + k);
        uint32_t hi2, lo2;
        split_pair(a.x, a.y, hi2, lo2);
        *(uint32_t*)(smem + SM_AHI + (size_t)(row * PADK + k) * 2) = hi2;
        *(uint32_t*)(smem + SM_ALO + (size_t)(row * PADK + k) * 2) = lo2;
    }
    __syncthreads();

    const int wm = wid & 3;          // 4 warps along M: 32 rows each
    const int wn = wid >> 2;         // 2 warps along N: 64 cols each

    float acc[2][8][4];
#pragma unroll
    for (int mt = 0; mt < 2; mt++)
#pragma unroll
        for (int nt = 0; nt < 8; nt++)
#pragma unroll
            for (int i = 0; i < 4; i++) acc[mt][nt][i] = 0.f;

    const int arow = (lane & 15);
    const int acolb = (lane >> 4) * 8;

#pragma unroll
    for (int cb = 0; cb < 3; cb++) {
        const char* As = smem + (cb == 2 ? SM_ALO : SM_AHI);
        const char* Bs = smem + (cb == 1 ? SM_BLO : SM_BHI);
#pragma unroll
        for (int k16 = 0; k16 < 8; k16++) {
            int k0 = k16 * 16;
            uint32_t afrag[2][4];
#pragma unroll
            for (int mt = 0; mt < 2; mt++) {
                int r = wm * 32 + mt * 16 + arow;
                ldmx4(afrag[mt], smem_u32(As + (size_t)(r * PADK + k0 + acolb) * 2));
            }
            uint32_t bfrag[8][2];
#pragma unroll
            for (int nt2 = 0; nt2 < 4; nt2++) {
                int r = k0 + arow;
                int c = wn * 64 + nt2 * 16 + acolb;
                uint32_t t[4];
                ldmx4t(t, smem_u32(Bs + (size_t)(r * PADK + c) * 2));
                bfrag[nt2 * 2][0] = t[0]; bfrag[nt2 * 2][1] = t[1];
                bfrag[nt2 * 2 + 1][0] = t[2]; bfrag[nt2 * 2 + 1][1] = t[3];
            }
#pragma unroll
            for (int mt = 0; mt < 2; mt++)
#pragma unroll
                for (int nt = 0; nt < 8; nt++)
                    mma16816(acc[mt][nt], afrag[mt], bfrag[nt]);
        }
    }

    // epilogue
    const float* bs = (const float*)(smem + SM_BIAS);
    int r0 = rowBase + wm * 32 + (lane >> 2);
    int cb0 = wn * 64 + (lane & 3) * 2;
#pragma unroll
    for (int mt = 0; mt < 2; mt++) {
#pragma unroll
        for (int half = 0; half < 2; half++) {
            int row = r0 + mt * 16 + half * 8;
            if (row < M) {
                float* crow = Cb + (size_t)row * D;
#pragma unroll
                for (int nt = 0; nt < 8; nt++) {
                    int col = cb0 + nt * 8;
                    float2 v = { acc[mt][nt][half * 2] + bs[col],
                                 acc[mt][nt][half * 2 + 1] + bs[col + 1] };
                    *(float2*)(crow + col) = v;
                }
            }
        }
    }
}

// ---------------- zero init ----------------
__global__ void zero_kernel() {
    int i = blockIdx.x * blockDim.x + threadIdx.x;
    if (i < NN) { g_srccnt[i] = 0; g_dstcnt[i] = 0; }
    if (i < D)  { g_bnsum[i] = 0.f; g_bnssum[i] = 0.f; }
}

// ---------------- BatchNorm ----------------
__global__ void bn_stats(const float* __restrict__ h) {
    int c = threadIdx.x;
    float s = 0.f, ss = 0.f;
    for (int r = blockIdx.x; r < NN; r += gridDim.x) {
        float v = h[(size_t)r * D + c];
        s += v; ss += v * v;
    }
    atomicAdd(&g_bnsum[c], s);
    atomicAdd(&g_bnssum[c], ss);
}

__global__ void bn_apply(const float* __restrict__ in, float* __restrict__ out,
                         const float* __restrict__ g, const float* __restrict__ b) {
    int i = blockIdx.x * blockDim.x + threadIdx.x;
    if (i >= NN * D) return;
    int c = i & (D - 1);
    float mu = g_bnsum[c] * (1.f / NN);
    float var = g_bnssum[c] * (1.f / NN) - mu * mu;
    float v = (in[i] - mu) * rsqrtf(var + 1e-5f) * g[c] + b[c];
    out[i] = fmaxf(v, 0.f);
}

// ---------------- graph preprocessing ----------------
__global__ void count_edges(const int* __restrict__ ei, int E) {
    int e = blockIdx.x * blockDim.x + threadIdx.x;
    if (e >= E) return;
    atomicAdd(&g_dstcnt[ei[e]], 1);
    atomicAdd(&g_srccnt[ei[E + e]], 1);
}

__global__ void dis_kernel() {
    int i = blockIdx.x * blockDim.x + threadIdx.x;
    if (i >= NN) return;
    int d = g_srccnt[i];
    g_dis[i] = (d > 0) ? rsqrtf((float)d) : 0.f;
}

__global__ void scan_kernel() {
    __shared__ int sh[1024];
    int tid = threadIdx.x;
    int carry = 0;
    for (int base = 0; base < NN; base += 1024) {
        int i = base + tid;
        int v = (i < NN) ? g_dstcnt[i] : 0;
        sh[tid] = v;
        __syncthreads();
        for (int o = 1; o < 1024; o <<= 1) {
            int x = (tid >= o) ? sh[tid - o] : 0;
            __syncthreads();
            sh[tid] += x;
            __syncthreads();
        }
        int incl = sh[tid];
        if (i < NN) {
            int ex = carry + incl - v;
            g_rowoff[i] = ex;
            g_cursor[i] = ex;
        }
        int tot = sh[1023];
        __syncthreads();
        carry += tot;
    }
    if (tid == 0) g_rowoff[NN] = carry;
}

__global__ void scatter_kernel(const int* __restrict__ ei, const int* __restrict__ ety, int E) {
    int e = blockIdx.x * blockDim.x + threadIdx.x;
    if (e >= E) return;
    int dst = ei[e];
    int src = ei[E + e];
    int r = ety[e];
    int pos = atomicAdd(&g_cursor[dst], 1);
    g_pack[pos] = src | (r << 16);
    g_norm[pos] = g_dis[dst] * g_dis[src];
}

// ---------------- edge aggregation: warp per dst node ----------------
__global__ __launch_bounds__(256) void aggregate(
    const float* __restrict__ xlin, const float* __restrict__ y, float* __restrict__ z)
{
    int w = (blockIdx.x * blockDim.x + threadIdx.x) >> 5;
    int lane = threadIdx.x & 31;
    if (w >= NN) return;
    int beg = g_rowoff[w], end = g_rowoff[w + 1];

    float4 gz = {0.f, 0.f, 0.f, 0.f};
    float4 sz = {0.f, 0.f, 0.f, 0.f};
    float4 tz = {0.f, 0.f, 0.f, 0.f};

    for (int e = beg; e < end; e++) {
        int pk = g_pack[e];
        float nm = g_norm[e];
        int src = pk & 0xFFFF;
        int r = pk >> 16;
        float4 xv = *(const float4*)(xlin + (size_t)src * D + lane * 4);
        float4 rv = *(const float4*)(y + ((size_t)r * NN + (size_t)src) * D + lane * 4);
        gz.x = fmaf(xv.x, nm, gz.x); gz.y = fmaf(xv.y, nm, gz.y);
        gz.z = fmaf(xv.z, nm, gz.z); gz.w = fmaf(xv.w, nm, gz.w);
        float e0 = __expf(rv.x), e1 = __expf(rv.y), e2 = __expf(rv.z), e3 = __expf(rv.w);
        sz.x += e0; sz.y += e1; sz.z += e2; sz.w += e3;
        tz.x = fmaf(rv.x, e0, tz.x); tz.y = fmaf(rv.y, e1, tz.y);
        tz.z = fmaf(rv.z, e2, tz.z); tz.w = fmaf(rv.w, e3, tz.w);
    }

    float4 o;
    if (end > beg) {
        o.x = gz.x + 0.1f * fmaxf(tz.x / sz.x, 0.f);
        o.y = gz.y + 0.1f * fmaxf(tz.y / sz.y, 0.f);
        o.z = gz.z + 0.1f * fmaxf(tz.z / sz.z, 0.f);
        o.w = gz.w + 0.1f * fmaxf(tz.w / sz.w, 0.f);
    } else {
        o = gz;
    }
    *(float4*)(z + (size_t)w * D + lane * 4) = o;
}

// ---------------- final gather + exact GELU ----------------
__global__ void gather_gelu(const float* __restrict__ h, const int* __restrict__ idx,
                            float* __restrict__ out, int NI) {
    int i = blockIdx.x * blockDim.x + threadIdx.x;
    if (i >= NI * D) return;
    int row = idx[i >> 7];
    float v = h[(size_t)row * D + (i & (D - 1))];
    out[i] = 0.5f * v * (1.0f + erff(v * 0.70710678118654752f));
}

// ---------------- launch ----------------
extern "C" void kernel_launch(void* const* d_in, const int* in_sizes, int n_in,
                              void* d_out, int out_size) {
    const float* x      = (const float*)d_in[0];
    const int*   ei     = (const int*)d_in[1];
    const int*   ety    = (const int*)d_in[2];
    const int*   idx    = (const int*)d_in[4];
    const float* proj_w = (const float*)d_in[5];
    const float* proj_b = (const float*)d_in[6];
    const float* bn_g   = (const float*)d_in[7];
    const float* bn_b   = (const float*)d_in[8];
    const float* win_w[2]  = { (const float*)d_in[9],  (const float*)d_in[14] };
    const float* win_b[2]  = { (const float*)d_in[10], (const float*)d_in[15] };
    const float* wrel[2]   = { (const float*)d_in[11], (const float*)d_in[16] };
    const float* cout_w[2] = { (const float*)d_in[12], (const float*)d_in[17] };
    const float* cout_b[2] = { (const float*)d_in[13], (const float*)d_in[18] };

    const int E  = in_sizes[1] / 2;
    const int NI = in_sizes[4];
    float* out = (float*)d_out;

    float *buf0, *buf1, *xlin, *y, *z;
    unsigned char* wbuf;
    cudaGetSymbolAddress((void**)&buf0, g_buf0);
    cudaGetSymbolAddress((void**)&buf1, g_buf1);
    cudaGetSymbolAddress((void**)&xlin, g_xlin);
    cudaGetSymbolAddress((void**)&y,    g_y);
    cudaGetSymbolAddress((void**)&z,    g_z);
    cudaGetSymbolAddress((void**)&wbuf, g_w);

    cudaFuncSetAttribute(gemm_mma, cudaFuncAttributeMaxDynamicSharedMemorySize, SM_TOTAL);

    const int GB = (NN + 127) / 128;

    zero_kernel<<<(NN + 255) / 256, 256>>>();

    // weight prep: slots 0=proj, 1=win0, 2..6=wrel0, 7=cout0, 8=win1, 9..13=wrel1, 14=cout1
    prep_w<<<1, 256>>>(proj_w, 0);
    prep_w<<<1, 256>>>(win_w[0], 1);
    prep_w<<<RELS, 256>>>(wrel[0], 2);
    prep_w<<<1, 256>>>(cout_w[0], 7);
    prep_w<<<1, 256>>>(win_w[1], 8);
    prep_w<<<RELS, 256>>>(wrel[1], 9);
    prep_w<<<1, 256>>>(cout_w[1], 14);

    // input projection -> BN (batch stats) -> relu
    gemm_mma<<<dim3(GB, 1, 1), 256, SM_TOTAL>>>(x, wbuf + 0 * WBYTES, proj_b, buf0, NN, 0);
    bn_stats<<<256, 128>>>(buf0);
    bn_apply<<<(NN * D + 255) / 256, 256>>>(buf0, buf1, bn_g, bn_b);

    // graph preprocessing
    count_edges<<<(E + 511) / 512, 512>>>(ei, E);
    dis_kernel<<<(NN + 255) / 256, 256>>>();
    scan_kernel<<<1, 1024>>>();
    scatter_kernel<<<(E + 511) / 512, 512>>>(ei, ety, E);

    const float* hin = buf1;
    float* hout = buf0;
    const int winm[2] = {1, 8}, wrelm[2] = {2, 9}, coutm[2] = {7, 14};
    for (int L = 0; L < 2; L++) {
        gemm_mma<<<dim3(GB, 1, 1), 256, SM_TOTAL>>>(hin, wbuf + (size_t)winm[L] * WBYTES, win_b[L], xlin, NN, 0);
        gemm_mma<<<dim3(GB, 1, RELS), 256, SM_TOTAL>>>(xlin, wbuf + (size_t)wrelm[L] * WBYTES, nullptr, y, NN, (long long)NN * D);
        aggregate<<<(NN * 32 + 255) / 256, 256>>>(xlin, y, z);
        gemm_mma<<<dim3(GB, 1, 1), 256, SM_TOTAL>>>(z, wbuf + (size_t)coutm[L] * WBYTES, cout_b[L], hout, NN, 0);
        float* t = (float*)hin; hin = hout; hout = t;
    }

    gather_gelu<<<(NI * D + 255) / 256, 256>>>(hin, idx, out, NI);
}

// round 4
// speedup vs baseline: 1.1660x; 1.0135x over previous
#include <cuda_runtime.h>
#include <cuda_bf16.h>
#include <cuda_fp16.h>
#include <math.h>
#include <stdint.h>

#define NN 48758
#define EE 750000
#define D 128
#define RELS 5
#define NMAT 15
#define PADK 136                 // padded row (elements) -> 272B stride, conflict-free ldmatrix
#define WBYTES 69632             // per-matrix prepped weight bytes (hi 34816 + lo 34816)
#define NB 48                    // scan blocks (48*1024 >= NN)

// ---------------- static device scratch ----------------
__device__ float g_buf0[NN * D];
__device__ float g_buf1[NN * D];
__device__ float g_xlin[NN * D];
__device__ __half g_yh[(size_t)RELS * NN * D];
__device__ float g_z[NN * D];
__device__ float g_bnsum[D];
__device__ float g_bnssum[D];
__device__ int   g_srccnt[NN];
__device__ int   g_dstcnt[NN];
__device__ float g_dis[NN];
__device__ int   g_rowoff[NN + 1];
__device__ int   g_cursor[NN];
__device__ int   g_scanloc[NN];
__device__ int   g_bsum[NB];
__device__ int   g_boff[NB];
__device__ int   g_pack[EE];
__device__ float g_norm[EE];
__device__ unsigned char g_w[(size_t)NMAT * WBYTES];
__device__ float g_ybias[2 * RELS * D];

// ---------------- helpers ----------------
__device__ __forceinline__ uint32_t smem_u32(const void* p) {
    uint32_t a;
    asm("{ .reg .u64 t; cvta.to.shared.u64 t, %1; cvt.u32.u64 %0, t; }" : "=r"(a) : "l"(p));
    return a;
}
__device__ __forceinline__ uint32_t pack_bf2(__nv_bfloat16 lo, __nv_bfloat16 hi) {
    return ((uint32_t)__bfloat16_as_ushort(hi) << 16) | (uint32_t)__bfloat16_as_ushort(lo);
}
__device__ __forceinline__ void split_pair(float x0, float x1, uint32_t& hi2, uint32_t& lo2) {
    __nv_bfloat16 h0 = __float2bfloat16(x0), h1 = __float2bfloat16(x1);
    __nv_bfloat16 l0 = __float2bfloat16(x0 - __bfloat162float(h0));
    __nv_bfloat16 l1 = __float2bfloat16(x1 - __bfloat162float(h1));
    hi2 = pack_bf2(h0, h1);
    lo2 = pack_bf2(l0, l1);
}
__device__ __forceinline__ void ldmx4(uint32_t* r, uint32_t addr) {
    asm volatile("ldmatrix.sync.aligned.m8n8.x4.shared.b16 {%0,%1,%2,%3}, [%4];"
                 : "=r"(r[0]), "=r"(r[1]), "=r"(r[2]), "=r"(r[3]) : "r"(addr));
}
__device__ __forceinline__ void ldmx4t(uint32_t* r, uint32_t addr) {
    asm volatile("ldmatrix.sync.aligned.m8n8.x4.trans.shared.b16 {%0,%1,%2,%3}, [%4];"
                 : "=r"(r[0]), "=r"(r[1]), "=r"(r[2]), "=r"(r[3]) : "r"(addr));
}
__device__ __forceinline__ void mma16816(float* c, const uint32_t* a, const uint32_t* b) {
    asm volatile(
        "mma.sync.aligned.m16n8k16.row.col.f32.bf16.bf16.f32 "
        "{%0,%1,%2,%3}, {%4,%5,%6,%7}, {%8,%9}, {%0,%1,%2,%3};"
        : "+f"(c[0]), "+f"(c[1]), "+f"(c[2]), "+f"(c[3])
        : "r"(a[0]), "r"(a[1]), "r"(a[2]), "r"(a[3]), "r"(b[0]), "r"(b[1]));
}

// ---------------- merged prep: 15 blocks, direct splits + composite win@wrel ----------------
// slots: 0=proj, 1=win0, 2..6=comp0_r, 7=cout0, 8=win1, 9..13=comp1_r, 14=cout1
__device__ void split_direct(const float* __restrict__ W, unsigned char* dst) {
    for (int idx = threadIdx.x; idx < 128 * 64; idx += blockDim.x) {
        int k = idx >> 6, n = (idx & 63) * 2;
        uint32_t hi2, lo2;
        split_pair(W[k * 128 + n], W[k * 128 + n + 1], hi2, lo2);
        *(uint32_t*)(dst + (size_t)(k * PADK + n) * 2) = hi2;
        *(uint32_t*)(dst + 34816 + (size_t)(k * PADK + n) * 2) = lo2;
    }
}

__global__ void prep_all(
    const float* __restrict__ proj,
    const float* __restrict__ win0, const float* __restrict__ wrel0,
    const float* __restrict__ cout0,
    const float* __restrict__ win1, const float* __restrict__ wrel1,
    const float* __restrict__ cout1,
    const float* __restrict__ win0b, const float* __restrict__ win1b)
{
    extern __shared__ float ws[];  // 16384 floats (64KB)
    int b = blockIdx.x, tid = threadIdx.x;

    if (b == 0)  { split_direct(proj,  g_w + 0 * (size_t)WBYTES);  return; }
    if (b == 1)  { split_direct(win0,  g_w + 1 * (size_t)WBYTES);  return; }
    if (b == 7)  { split_direct(cout0, g_w + 7 * (size_t)WBYTES);  return; }
    if (b == 8)  { split_direct(win1,  g_w + 8 * (size_t)WBYTES);  return; }
    if (b == 14) { split_direct(cout1, g_w + 14 * (size_t)WBYTES); return; }

    // composite: Wc = win @ wrel_r ; bias bc = win_b @ wrel_r
    int L = (b >= 9) ? 1 : 0;
    int r = L ? (b - 9) : (b - 2);
    const float* win = L ? win1 : win0;
    const float* wrl = (L ? wrel1 : wrel0) + (size_t)r * 16384;
    const float* wb  = L ? win1b : win0b;
    unsigned char* dst = g_w + (size_t)b * WBYTES;

    for (int i = tid; i < 4096; i += blockDim.x)
        ((float4*)ws)[i] = ((const float4*)wrl)[i];
    __syncthreads();

    int n = tid & 127;
    int kbase = (tid >> 7) * 64;
    for (int ko = 0; ko < 64; ko++) {
        int k = kbase + ko;
        const float* wr = win + (size_t)k * 128;
        float acc = 0.f;
#pragma unroll 8
        for (int j = 0; j < 128; j++) acc = fmaf(wr[j], ws[j * 128 + n], acc);
        __nv_bfloat16 h = __float2bfloat16(acc);
        __nv_bfloat16 l = __float2bfloat16(acc - __bfloat162float(h));
        *(unsigned short*)(dst + (size_t)(k * PADK + n) * 2) = __bfloat16_as_ushort(h);
        *(unsigned short*)(dst + 34816 + (size_t)(k * PADK + n) * 2) = __bfloat16_as_ushort(l);
    }
    if (tid < 128) {
        float acc = 0.f;
#pragma unroll 8
        for (int k = 0; k < 128; k++) acc = fmaf(wb[k], ws[k * 128 + tid], acc);
        g_ybias[(L * RELS + r) * D + tid] = acc;
    }
}

// ---------------- shared GEMM core ----------------
#define SM_AHI  0
#define SM_ALO  34816
#define SM_BHI  69632
#define SM_BLO  104448
#define SM_BIAS 139264
#define SM_TOTAL 139776

__device__ __forceinline__ void gemm_core(
    char* smem, const float* __restrict__ A, const unsigned char* __restrict__ Wb,
    const float* __restrict__ bias, int rowBase, int M, float acc[2][8][4],
    int wm, int wn, int lane)
{
    int tid = threadIdx.x;
    for (int i = tid; i < WBYTES / 16; i += 256)
        ((float4*)(smem + SM_BHI))[i] = ((const float4*)Wb)[i];
    if (tid < 128) ((float*)(smem + SM_BIAS))[tid] = bias ? bias[tid] : 0.f;
    for (int idx = tid; idx < 128 * 64; idx += 256) {
        int row = idx >> 6, k = (idx & 63) * 2;
        int gr = rowBase + row; if (gr >= M) gr = M - 1;
        float2 a = *(const float2*)(A + (size_t)gr * D + k);
        uint32_t hi2, lo2;
        split_pair(a.x, a.y, hi2, lo2);
        *(uint32_t*)(smem + SM_AHI + (size_t)(row * PADK + k) * 2) = hi2;
        *(uint32_t*)(smem + SM_ALO + (size_t)(row * PADK + k) * 2) = lo2;
    }
    __syncthreads();

#pragma unroll
    for (int mt = 0; mt < 2; mt++)
#pragma unroll
        for (int nt = 0; nt < 8; nt++)
#pragma unroll
            for (int i = 0; i < 4; i++) acc[mt][nt][i] = 0.f;

    const int arow = (lane & 15);
    const int acolb = (lane >> 4) * 8;

#pragma unroll
    for (int cb = 0; cb < 3; cb++) {
        const char* As = smem + (cb == 2 ? SM_ALO : SM_AHI);
        const char* Bs = smem + (cb == 1 ? SM_BLO : SM_BHI);
#pragma unroll
        for (int k16 = 0; k16 < 8; k16++) {
            int k0 = k16 * 16;
            uint32_t afrag[2][4];
#pragma unroll
            for (int mt = 0; mt < 2; mt++) {
                int rr = wm * 32 + mt * 16 + arow;
                ldmx4(afrag[mt], smem_u32(As + (size_t)(rr * PADK + k0 + acolb) * 2));
            }
            uint32_t bfrag[8][2];
#pragma unroll
            for (int nt2 = 0; nt2 < 4; nt2++) {
                int rr = k0 + arow;
                int c = wn * 64 + nt2 * 16 + acolb;
                uint32_t t[4];
                ldmx4t(t, smem_u32(Bs + (size_t)(rr * PADK + c) * 2));
                bfrag[nt2 * 2][0] = t[0]; bfrag[nt2 * 2][1] = t[1];
                bfrag[nt2 * 2 + 1][0] = t[2]; bfrag[nt2 * 2 + 1][1] = t[3];
            }
#pragma unroll
            for (int mt = 0; mt < 2; mt++)
#pragma unroll
                for (int nt = 0; nt < 8; nt++)
                    mma16816(acc[mt][nt], afrag[mt], bfrag[nt]);
        }
    }
}

// plain fp32-out GEMM (proj / cout)
__global__ __launch_bounds__(256, 1) void gemm_mma(
    const float* __restrict__ A, const unsigned char* __restrict__ Wp,
    const float* __restrict__ bias, float* __restrict__ C, int M)
{
    extern __shared__ char smem[];
    int tid = threadIdx.x, wid = tid >> 5, lane = tid & 31;
    int wm = wid & 3, wn = wid >> 2;
    int rowBase = blockIdx.x * 128;
    float acc[2][8][4];
    gemm_core(smem, A, Wp, bias, rowBase, M, acc, wm, wn, lane);

    const float* bs = (const float*)(smem + SM_BIAS);
    int r0 = rowBase + wm * 32 + (lane >> 2);
    int cb0 = wn * 64 + (lane & 3) * 2;
#pragma unroll
    for (int mt = 0; mt < 2; mt++)
#pragma unroll
        for (int half = 0; half < 2; half++) {
            int row = r0 + mt * 16 + half * 8;
            if (row < M) {
                float* crow = C + (size_t)row * D;
#pragma unroll
                for (int nt = 0; nt < 8; nt++) {
                    int col = cb0 + nt * 8;
                    float2 v = { acc[mt][nt][half * 2] + bs[col],
                                 acc[mt][nt][half * 2 + 1] + bs[col + 1] };
                    *(float2*)(crow + col) = v;
                }
            }
        }
}

// fused per-layer GEMM: z=0 -> xlin fp32 (bias=win_b); z=1..5 -> y_r fp16 (bias=ybias[r])
__global__ __launch_bounds__(256, 1) void gemm_fused(
    const float* __restrict__ A, const unsigned char* __restrict__ Wbase,
    const float* __restrict__ winb, const float* __restrict__ ybias,
    float* __restrict__ xlin, __half* __restrict__ yh, int M)
{
    extern __shared__ char smem[];
    int z = blockIdx.z;
    int tid = threadIdx.x, wid = tid >> 5, lane = tid & 31;
    int wm = wid & 3, wn = wid >> 2;
    int rowBase = blockIdx.x * 128;
    const unsigned char* Wp = Wbase + (size_t)z * WBYTES;
    const float* bias = (z == 0) ? winb : (ybias + (size_t)(z - 1) * D);

    float acc[2][8][4];
    gemm_core(smem, A, Wp, bias, rowBase, M, acc, wm, wn, lane);

    const float* bs = (const float*)(smem + SM_BIAS);
    int r0 = rowBase + wm * 32 + (lane >> 2);
    int cb0 = wn * 64 + (lane & 3) * 2;

    if (z == 0) {
#pragma unroll
        for (int mt = 0; mt < 2; mt++)
#pragma unroll
            for (int half = 0; half < 2; half++) {
                int row = r0 + mt * 16 + half * 8;
                if (row < M) {
                    float* crow = xlin + (size_t)row * D;
#pragma unroll
                    for (int nt = 0; nt < 8; nt++) {
                        int col = cb0 + nt * 8;
                        float2 v = { acc[mt][nt][half * 2] + bs[col],
                                     acc[mt][nt][half * 2 + 1] + bs[col + 1] };
                        *(float2*)(crow + col) = v;
                    }
                }
            }
    } else {
        __half* Y = yh + (size_t)(z - 1) * NN * D;
#pragma unroll
        for (int mt = 0; mt < 2; mt++)
#pragma unroll
            for (int half = 0; half < 2; half++) {
                int row = r0 + mt * 16 + half * 8;
                if (row < M) {
                    __half* crow = Y + (size_t)row * D;
#pragma unroll
                    for (int nt = 0; nt < 8; nt++) {
                        int col = cb0 + nt * 8;
                        __half2 v = __floats2half2_rn(acc[mt][nt][half * 2] + bs[col],
                                                      acc[mt][nt][half * 2 + 1] + bs[col + 1]);
                        *(__half2*)(crow + col) = v;
                    }
                }
            }
    }
}

// ---------------- zero init ----------------
__global__ void zero_kernel() {
    int i = blockIdx.x * blockDim.x + threadIdx.x;
    if (i < NN) { g_srccnt[i] = 0; g_dstcnt[i] = 0; }
    if (i < D)  { g_bnsum[i] = 0.f; g_bnssum[i] = 0.f; }
}

// ---------------- BatchNorm ----------------
__global__ void bn_stats(const float* __restrict__ h) {
    int c = threadIdx.x;
    float s = 0.f, ss = 0.f;
    for (int r = blockIdx.x; r < NN; r += gridDim.x) {
        float v = h[(size_t)r * D + c];
        s += v; ss += v * v;
    }
    atomicAdd(&g_bnsum[c], s);
    atomicAdd(&g_bnssum[c], ss);
}

__global__ void bn_apply(const float* __restrict__ in, float* __restrict__ out,
                         const float* __restrict__ g, const float* __restrict__ b) {
    int i = blockIdx.x * blockDim.x + threadIdx.x;
    if (i >= NN * D) return;
    int c = i & (D - 1);
    float mu = g_bnsum[c] * (1.f / NN);
    float var = g_bnssum[c] * (1.f / NN) - mu * mu;
    float v = (in[i] - mu) * rsqrtf(var + 1e-5f) * g[c] + b[c];
    out[i] = fmaxf(v, 0.f);
}

// ---------------- graph preprocessing ----------------
__global__ void count_edges(const int* __restrict__ ei, int E) {
    int e = blockIdx.x * blockDim.x + threadIdx.x;
    if (e >= E) return;
    atomicAdd(&g_dstcnt[ei[e]], 1);
    atomicAdd(&g_srccnt[ei[E + e]], 1);
}

__global__ void dis_kernel() {
    int i = blockIdx.x * blockDim.x + threadIdx.x;
    if (i >= NN) return;
    int d = g_srccnt[i];
    g_dis[i] = (d > 0) ? rsqrtf((float)d) : 0.f;
}

// 3-phase scan
__global__ void scan_local() {
    __shared__ int sh[1024];
    int b = blockIdx.x, tid = threadIdx.x;
    int i = b * 1024 + tid;
    int v = (i < NN) ? g_dstcnt[i] : 0;
    sh[tid] = v;
    __syncthreads();
    for (int o = 1; o < 1024; o <<= 1) {
        int x = (tid >= o) ? sh[tid - o] : 0;
        __syncthreads();
        sh[tid] += x;
        __syncthreads();
    }
    if (i < NN) g_scanloc[i] = sh[tid];
    if (tid == 1023) g_bsum[b] = sh[1023];
}
__global__ void scan_bsum() {
    __shared__ int sh[NB];
    int tid = threadIdx.x;
    if (tid < NB) sh[tid] = g_bsum[tid];
    __syncthreads();
    if (tid == 0) {
        int run = 0;
        for (int b = 0; b < NB; b++) { g_boff[b] = run; run += sh[b]; }
        g_rowoff[NN] = run;
    }
}
__global__ void scan_add() {
    int i = blockIdx.x * blockDim.x + threadIdx.x;
    if (i >= NN) return;
    int ex = g_boff[i >> 10] + g_scanloc[i] - g_dstcnt[i];
    g_rowoff[i] = ex;
    g_cursor[i] = ex;
}

__global__ void scatter_kernel(const int* __restrict__ ei, const int* __restrict__ ety, int E) {
    int e = blockIdx.x * blockDim.x + threadIdx.x;
    if (e >= E) return;
    int dst = ei[e];
    int src = ei[E + e];
    int r = ety[e];
    int pos = atomicAdd(&g_cursor[dst], 1);
    g_pack[pos] = src | (r << 16);
    g_norm[pos] = g_dis[dst] * g_dis[src];
}

// ---------------- edge aggregation: warp per dst node, fp16 y ----------------
__global__ __launch_bounds__(256) void aggregate(
    const float* __restrict__ xlin, const __half* __restrict__ yh, float* __restrict__ z)
{
    int w = (blockIdx.x * blockDim.x + threadIdx.x) >> 5;
    int lane = threadIdx.x & 31;
    if (w >= NN) return;
    int beg = g_rowoff[w], end = g_rowoff[w + 1];

    float4 gz = {0.f, 0.f, 0.f, 0.f};
    float4 sz = {0.f, 0.f, 0.f, 0.f};
    float4 tz = {0.f, 0.f, 0.f, 0.f};

    for (int e = beg; e < end; e++) {
        int pk = g_pack[e];
        float nm = g_norm[e];
        int src = pk & 0xFFFF;
        int r = pk >> 16;
        float4 xv = *(const float4*)(xlin + (size_t)src * D + lane * 4);
        uint2 yp = *(const uint2*)(yh + ((size_t)r * NN + (size_t)src) * D + lane * 4);
        float2 y0 = __half22float2(*(__half2*)&yp.x);
        float2 y1 = __half22float2(*(__half2*)&yp.y);
        gz.x = fmaf(xv.x, nm, gz.x); gz.y = fmaf(xv.y, nm, gz.y);
        gz.z = fmaf(xv.z, nm, gz.z); gz.w = fmaf(xv.w, nm, gz.w);
        float e0 = __expf(y0.x), e1 = __expf(y0.y), e2 = __expf(y1.x), e3 = __expf(y1.y);
        sz.x += e0; sz.y += e1; sz.z += e2; sz.w += e3;
        tz.x = fmaf(y0.x, e0, tz.x); tz.y = fmaf(y0.y, e1, tz.y);
        tz.z = fmaf(y1.x, e2, tz.z); tz.w = fmaf(y1.y, e3, tz.w);
    }

    float4 o;
    if (end > beg) {
        o.x = gz.x + 0.1f * fmaxf(tz.x / sz.x, 0.f);
        o.y = gz.y + 0.1f * fmaxf(tz.y / sz.y, 0.f);
        o.z = gz.z + 0.1f * fmaxf(tz.z / sz.z, 0.f);
        o.w = gz.w + 0.1f * fmaxf(tz.w / sz.w, 0.f);
    } else {
        o = gz;
    }
    *(float4*)(z + (size_t)w * D + lane * 4) = o;
}

// ---------------- final gather + exact GELU ----------------
__global__ void gather_gelu(const float* __restrict__ h, const int* __restrict__ idx,
                            float* __restrict__ out, int NI) {
    int i = blockIdx.x * blockDim.x + threadIdx.x;
    if (i >= NI * D) return;
    int row = idx[i >> 7];
    float v = h[(size_t)row * D + (i & (D - 1))];
    out[i] = 0.5f * v * (1.0f + erff(v * 0.70710678118654752f));
}

// ---------------- launch ----------------
extern "C" void kernel_launch(void* const* d_in, const int* in_sizes, int n_in,
                              void* d_out, int out_size) {
    const float* x      = (const float*)d_in[0];
    const int*   ei     = (const int*)d_in[1];
    const int*   ety    = (const int*)d_in[2];
    const int*   idx    = (const int*)d_in[4];
    const float* proj_w = (const float*)d_in[5];
    const float* proj_b = (const float*)d_in[6];
    const float* bn_g   = (const float*)d_in[7];
    const float* bn_b   = (const float*)d_in[8];
    const float* win_w[2]  = { (const float*)d_in[9],  (const float*)d_in[14] };
    const float* win_b[2]  = { (const float*)d_in[10], (const float*)d_in[15] };
    const float* wrel[2]   = { (const float*)d_in[11], (const float*)d_in[16] };
    const float* cout_w[2] = { (const float*)d_in[12], (const float*)d_in[17] };
    const float* cout_b[2] = { (const float*)d_in[13], (const float*)d_in[18] };

    const int E  = in_sizes[1] / 2;
    const int NI = in_sizes[4];
    float* out = (float*)d_out;

    float *buf0, *buf1, *xlin, *z, *ybias;
    __half* yh;
    unsigned char* wbuf;
    cudaGetSymbolAddress((void**)&buf0, g_buf0);
    cudaGetSymbolAddress((void**)&buf1, g_buf1);
    cudaGetSymbolAddress((void**)&xlin, g_xlin);
    cudaGetSymbolAddress((void**)&yh,   g_yh);
    cudaGetSymbolAddress((void**)&z,    g_z);
    cudaGetSymbolAddress((void**)&wbuf, g_w);
    cudaGetSymbolAddress((void**)&ybias, g_ybias);

    cudaFuncSetAttribute(gemm_mma, cudaFuncAttributeMaxDynamicSharedMemorySize, SM_TOTAL);
    cudaFuncSetAttribute(gemm_fused, cudaFuncAttributeMaxDynamicSharedMemorySize, SM_TOTAL);
    cudaFuncSetAttribute(prep_all, cudaFuncAttributeMaxDynamicSharedMemorySize, 65536);

    const int GB = (NN + 127) / 128;

    zero_kernel<<<(NN + 255) / 256, 256>>>();
    prep_all<<<NMAT, 256, 65536>>>(proj_w, win_w[0], wrel[0], cout_w[0],
                                   win_w[1], wrel[1], cout_w[1], win_b[0], win_b[1]);

    // input projection -> BN (batch stats) -> relu
    gemm_mma<<<GB, 256, SM_TOTAL>>>(x, wbuf, proj_b, buf0, NN);
    bn_stats<<<256, 128>>>(buf0);
    bn_apply<<<(NN * D + 255) / 256, 256>>>(buf0, buf1, bn_g, bn_b);

    // graph preprocessing
    count_edges<<<(E + 511) / 512, 512>>>(ei, E);
    dis_kernel<<<(NN + 255) / 256, 256>>>();
    scan_local<<<NB, 1024>>>();
    scan_bsum<<<1, 64>>>();
    scan_add<<<(NN + 1023) / 1024, 1024>>>();
    scatter_kernel<<<(E + 511) / 512, 512>>>(ei, ety, E);

    const float* hin = buf1;
    float* hout = buf0;
    for (int L = 0; L < 2; L++) {
        gemm_fused<<<dim3(GB, 1, 6), 256, SM_TOTAL>>>(
            hin, wbuf + (size_t)(1 + L * 7) * WBYTES, win_b[L],
            ybias + (size_t)L * RELS * D, xlin, yh, NN);
        aggregate<<<(NN * 32 + 255) / 256, 256>>>(xlin, yh, z);
        gemm_mma<<<GB, 256, SM_TOTAL>>>(z, wbuf + (size_t)(7 + L * 7) * WBYTES, cout_b[L], hout, NN);
        float* t = (float*)hin; hin = hout; hout = t;
    }

    gather_gelu<<<(NI * D + 255) / 256, 256>>>(hin, idx, out, NI);
}

// round 5
// speedup vs baseline: 1.3343x; 1.1443x over previous
#include <cuda_runtime.h>
#include <cuda_bf16.h>
#include <cuda_fp16.h>
#include <math.h>
#include <stdint.h>

#define NN 48758
#define EE 750000
#define D 128
#define RELS 5
#define NMAT 15
#define PADK 136                 // padded row (elements) -> 272B stride, conflict-free ldmatrix
#define WBYTES 69632             // per-matrix prepped weight bytes (hi 34816 + lo 34816)
#define NB 48                    // scan blocks

// ---------------- static device scratch ----------------
__device__ __align__(256) float g_buf0[NN * D];
__device__ __align__(256) float g_buf1[NN * D];
__device__ __align__(256) float g_xlin[NN * D];
__device__ __align__(256) __half g_yh[(size_t)RELS * NN * D];
__device__ __align__(256) float g_z[NN * D];
__device__ float g_bnsum[D];
__device__ float g_bnssum[D];
__device__ int   g_srccnt[NN];
__device__ int   g_dstcnt[NN];
__device__ float g_dis[NN];
__device__ int   g_rowoff[NN + 1];
__device__ int   g_cursor[NN];
__device__ int   g_scanloc[NN];
__device__ int   g_bsum[NB];
__device__ int   g_boff[NB];
__device__ int   g_pack[EE];
__device__ float g_norm[EE];
__device__ __align__(256) unsigned char g_w[(size_t)NMAT * WBYTES];
__device__ float g_ybias[2 * RELS * D];

// ---------------- helpers ----------------
__device__ __forceinline__ uint32_t smem_u32(const void* p) {
    uint32_t a;
    asm("{ .reg .u64 t; cvta.to.shared.u64 t, %1; cvt.u32.u64 %0, t; }" : "=r"(a) : "l"(p));
    return a;
}
__device__ __forceinline__ uint32_t pack_bf2(__nv_bfloat16 lo, __nv_bfloat16 hi) {
    return ((uint32_t)__bfloat16_as_ushort(hi) << 16) | (uint32_t)__bfloat16_as_ushort(lo);
}
__device__ __forceinline__ void split_pair(float x0, float x1, uint32_t& hi2, uint32_t& lo2) {
    __nv_bfloat16 h0 = __float2bfloat16(x0), h1 = __float2bfloat16(x1);
    __nv_bfloat16 l0 = __float2bfloat16(x0 - __bfloat162float(h0));
    __nv_bfloat16 l1 = __float2bfloat16(x1 - __bfloat162float(h1));
    hi2 = pack_bf2(h0, h1);
    lo2 = pack_bf2(l0, l1);
}
__device__ __forceinline__ void ldmx4(uint32_t* r, uint32_t addr) {
    asm volatile("ldmatrix.sync.aligned.m8n8.x4.shared.b16 {%0,%1,%2,%3}, [%4];"
                 : "=r"(r[0]), "=r"(r[1]), "=r"(r[2]), "=r"(r[3]) : "r"(addr));
}
__device__ __forceinline__ void ldmx4t(uint32_t* r, uint32_t addr) {
    asm volatile("ldmatrix.sync.aligned.m8n8.x4.trans.shared.b16 {%0,%1,%2,%3}, [%4];"
                 : "=r"(r[0]), "=r"(r[1]), "=r"(r[2]), "=r"(r[3]) : "r"(addr));
}
__device__ __forceinline__ void mma16816(float* c, const uint32_t* a, const uint32_t* b) {
    asm volatile(
        "mma.sync.aligned.m16n8k16.row.col.f32.bf16.bf16.f32 "
        "{%0,%1,%2,%3}, {%4,%5,%6,%7}, {%8,%9}, {%0,%1,%2,%3};"
        : "+f"(c[0]), "+f"(c[1]), "+f"(c[2]), "+f"(c[3])
        : "r"(a[0]), "r"(a[1]), "r"(a[2]), "r"(a[3]), "r"(b[0]), "r"(b[1]));
}
__device__ __forceinline__ void cpasync16(uint32_t sdst, const void* gsrc) {
    asm volatile("cp.async.cg.shared.global [%0], [%1], 16;" :: "r"(sdst), "l"(gsrc) : "memory");
}
__device__ __forceinline__ void cp_commit() {
    asm volatile("cp.async.commit_group;" ::: "memory");
}

// ---------------- merged prep ----------------
// slots: 0=proj, 1=win0, 2..6=comp0_r, 7=cout0, 8=win1, 9..13=comp1_r, 14=cout1
__device__ void split_direct(const float* __restrict__ W, unsigned char* dst) {
    for (int idx = threadIdx.x; idx < 128 * 64; idx += blockDim.x) {
        int k = idx >> 6, n = (idx & 63) * 2;
        uint32_t hi2, lo2;
        split_pair(W[k * 128 + n], W[k * 128 + n + 1], hi2, lo2);
        *(uint32_t*)(dst + (size_t)(k * PADK + n) * 2) = hi2;
        *(uint32_t*)(dst + 34816 + (size_t)(k * PADK + n) * 2) = lo2;
    }
}

__global__ void prep_all(
    const float* __restrict__ proj,
    const float* __restrict__ win0, const float* __restrict__ wrel0,
    const float* __restrict__ cout0,
    const float* __restrict__ win1, const float* __restrict__ wrel1,
    const float* __restrict__ cout1,
    const float* __restrict__ win0b, const float* __restrict__ win1b)
{
    extern __shared__ float ws[];
    int b = blockIdx.x, tid = threadIdx.x;

    if (b == 0)  { split_direct(proj,  g_w + 0 * (size_t)WBYTES);  return; }
    if (b == 1)  { split_direct(win0,  g_w + 1 * (size_t)WBYTES);  return; }
    if (b == 7)  { split_direct(cout0, g_w + 7 * (size_t)WBYTES);  return; }
    if (b == 8)  { split_direct(win1,  g_w + 8 * (size_t)WBYTES);  return; }
    if (b == 14) { split_direct(cout1, g_w + 14 * (size_t)WBYTES); return; }

    int L = (b >= 9) ? 1 : 0;
    int r = L ? (b - 9) : (b - 2);
    const float* win = L ? win1 : win0;
    const float* wrl = (L ? wrel1 : wrel0) + (size_t)r * 16384;
    const float* wb  = L ? win1b : win0b;
    unsigned char* dst = g_w + (size_t)b * WBYTES;

    for (int i = tid; i < 4096; i += blockDim.x)
        ((float4*)ws)[i] = ((const float4*)wrl)[i];
    __syncthreads();

    int n = tid & 127;
    int kbase = (tid >> 7) * 64;
    for (int ko = 0; ko < 64; ko++) {
        int k = kbase + ko;
        const float* wr = win + (size_t)k * 128;
        float acc = 0.f;
#pragma unroll 8
        for (int j = 0; j < 128; j++) acc = fmaf(wr[j], ws[j * 128 + n], acc);
        __nv_bfloat16 h = __float2bfloat16(acc);
        __nv_bfloat16 l = __float2bfloat16(acc - __bfloat162float(h));
        *(unsigned short*)(dst + (size_t)(k * PADK + n) * 2) = __bfloat16_as_ushort(h);
        *(unsigned short*)(dst + 34816 + (size_t)(k * PADK + n) * 2) = __bfloat16_as_ushort(l);
    }
    if (tid < 128) {
        float acc = 0.f;
#pragma unroll 8
        for (int k = 0; k < 128; k++) acc = fmaf(wb[k], ws[k * 128 + tid], acc);
        g_ybias[(L * RELS + r) * D + tid] = acc;
    }
}

// ---------------- mma compute core (A smem base, B smem base) ----------------
__device__ __forceinline__ void mma_compute(
    const char* Abase, const char* Bbase, float acc[2][8][4], int wm, int wn, int lane)
{
#pragma unroll
    for (int mt = 0; mt < 2; mt++)
#pragma unroll
        for (int nt = 0; nt < 8; nt++)
#pragma unroll
            for (int i = 0; i < 4; i++) acc[mt][nt][i] = 0.f;

    const int arow = (lane & 15);
    const int acolb = (lane >> 4) * 8;

#pragma unroll
    for (int cb = 0; cb < 3; cb++) {
        const char* As = Abase + (cb == 2 ? 34816 : 0);
        const char* Bs = Bbase + (cb == 1 ? 34816 : 0);
#pragma unroll
        for (int k16 = 0; k16 < 8; k16++) {
            int k0 = k16 * 16;
            uint32_t afrag[2][4];
#pragma unroll
            for (int mt = 0; mt < 2; mt++) {
                int rr = wm * 32 + mt * 16 + arow;
                ldmx4(afrag[mt], smem_u32(As + (size_t)(rr * PADK + k0 + acolb) * 2));
            }
            uint32_t bfrag[8][2];
#pragma unroll
            for (int nt2 = 0; nt2 < 4; nt2++) {
                int rr = k0 + arow;
                int c = wn * 64 + nt2 * 16 + acolb;
                uint32_t t[4];
                ldmx4t(t, smem_u32(Bs + (size_t)(rr * PADK + c) * 2));
                bfrag[nt2 * 2][0] = t[0]; bfrag[nt2 * 2][1] = t[1];
                bfrag[nt2 * 2 + 1][0] = t[2]; bfrag[nt2 * 2 + 1][1] = t[3];
            }
#pragma unroll
            for (int mt = 0; mt < 2; mt++)
#pragma unroll
                for (int nt = 0; nt < 8; nt++)
                    mma16816(acc[mt][nt], afrag[mt], bfrag[nt]);
        }
    }
}

__device__ __forceinline__ void stage_A(char* smem, const float* __restrict__ A,
                                        int rowBase, int M, int aoff) {
    for (int idx = threadIdx.x; idx < 128 * 64; idx += 256) {
        int row = idx >> 6, k = (idx & 63) * 2;
        int gr = rowBase + row; if (gr >= M) gr = M - 1;
        float2 a = *(const float2*)(A + (size_t)gr * D + k);
        uint32_t hi2, lo2;
        split_pair(a.x, a.y, hi2, lo2);
        *(uint32_t*)(smem + aoff + (size_t)(row * PADK + k) * 2) = hi2;
        *(uint32_t*)(smem + aoff + 34816 + (size_t)(row * PADK + k) * 2) = lo2;
    }
}

// ---------------- single GEMM (proj / cout): C = A @ W + bias ----------------
#define SM_AHI  0
#define SM_BHI  69632
#define SM_BIAS 139264
#define SM_TOTAL 139776

__global__ __launch_bounds__(256, 1) void gemm_mma(
    const float* __restrict__ A, const unsigned char* __restrict__ Wp,
    const float* __restrict__ bias, float* __restrict__ C, int M)
{
    extern __shared__ char smem[];
    int tid = threadIdx.x, wid = tid >> 5, lane = tid & 31;
    int wm = wid & 3, wn = wid >> 2;
    int rowBase = blockIdx.x * 128;

    for (int i = tid; i < WBYTES / 16; i += 256)
        ((float4*)(smem + SM_BHI))[i] = ((const float4*)Wp)[i];
    if (tid < 128) ((float*)(smem + SM_BIAS))[tid] = bias[tid];
    stage_A(smem, A, rowBase, M, SM_AHI);
    __syncthreads();

    float acc[2][8][4];
    mma_compute(smem + SM_AHI, smem + SM_BHI, acc, wm, wn, lane);

    const float* bs = (const float*)(smem + SM_BIAS);
    int r0 = rowBase + wm * 32 + (lane >> 2);
    int cb0 = wn * 64 + (lane & 3) * 2;
#pragma unroll
    for (int mt = 0; mt < 2; mt++)
#pragma unroll
        for (int half = 0; half < 2; half++) {
            int row = r0 + mt * 16 + half * 8;
            if (row < M) {
                float* crow = C + (size_t)row * D;
#pragma unroll
                for (int nt = 0; nt < 8; nt++) {
                    int col = cb0 + nt * 8;
                    float2 v = { acc[mt][nt][half * 2] + bs[col],
                                 acc[mt][nt][half * 2 + 1] + bs[col + 1] };
                    *(float2*)(crow + col) = v;
                }
            }
        }
}

// ---------------- A-stationary 6-matrix GEMM with cp.async double-buffered B ----------------
// smem: A 0..69632 | B0 69632.. | B1 139264.. | bias 208896 (6*512) | total 211968
#define SM6_A    0
#define SM6_B0   69632
#define SM6_B1   139264
#define SM6_BIAS 208896
#define SM6_TOTAL 212000

__global__ __launch_bounds__(256, 1) void gemm6(
    const float* __restrict__ A, const unsigned char* __restrict__ Wbase,
    const float* __restrict__ winb, const float* __restrict__ ybias,
    float* __restrict__ xlin, __half* __restrict__ yh, int M)
{
    extern __shared__ char smem[];
    uint32_t sb = smem_u32(smem);
    int tid = threadIdx.x, wid = tid >> 5, lane = tid & 31;
    int wm = wid & 3, wn = wid >> 2;
    int rowBase = blockIdx.x * 128;

    // biases: [0..128)=winb, [128..768)=ybias
    if (tid < 128) ((float*)(smem + SM6_BIAS))[tid] = winb[tid];
    for (int i = tid; i < RELS * 128; i += 256)
        ((float*)(smem + SM6_BIAS))[128 + i] = ybias[i];

    // issue B0 prefetch
    for (int i = tid; i < WBYTES / 16; i += 256)
        cpasync16(sb + SM6_B0 + i * 16, Wbase + (size_t)i * 16);
    cp_commit();

    // stage A (split to hi/lo bf16)
    stage_A(smem, A, rowBase, M, SM6_A);

    int r0 = rowBase + wm * 32 + (lane >> 2);
    int cb0 = wn * 64 + (lane & 3) * 2;

#pragma unroll 1
    for (int z = 0; z < 6; z++) {
        int cur = z & 1;
        if (z < 5) {
            const unsigned char* Wn = Wbase + (size_t)(z + 1) * WBYTES;
            uint32_t bdst = sb + ((z + 1) & 1 ? SM6_B1 : SM6_B0);
            for (int i = tid; i < WBYTES / 16; i += 256)
                cpasync16(bdst + i * 16, Wn + (size_t)i * 16);
            cp_commit();
            asm volatile("cp.async.wait_group 1;" ::: "memory");
        } else {
            asm volatile("cp.async.wait_group 0;" ::: "memory");
        }
        __syncthreads();

        float acc[2][8][4];
        mma_compute(smem + SM6_A, smem + (cur ? SM6_B1 : SM6_B0), acc, wm, wn, lane);

        const float* bs = (const float*)(smem + SM6_BIAS) + z * 128;
        if (z == 0) {
#pragma unroll
            for (int mt = 0; mt < 2; mt++)
#pragma unroll
                for (int half = 0; half < 2; half++) {
                    int row = r0 + mt * 16 + half * 8;
                    if (row < M) {
                        float* crow = xlin + (size_t)row * D;
#pragma unroll
                        for (int nt = 0; nt < 8; nt++) {
                            int col = cb0 + nt * 8;
                            float2 v = { acc[mt][nt][half * 2] + bs[col],
                                         acc[mt][nt][half * 2 + 1] + bs[col + 1] };
                            *(float2*)(crow + col) = v;
                        }
                    }
                }
        } else {
            __half* Y = yh + (size_t)(z - 1) * NN * D;
#pragma unroll
            for (int mt = 0; mt < 2; mt++)
#pragma unroll
                for (int half = 0; half < 2; half++) {
                    int row = r0 + mt * 16 + half * 8;
                    if (row < M) {
                        __half* crow = Y + (size_t)row * D;
#pragma unroll
                        for (int nt = 0; nt < 8; nt++) {
                            int col = cb0 + nt * 8;
                            __half2 v = __floats2half2_rn(acc[mt][nt][half * 2] + bs[col],
                                                          acc[mt][nt][half * 2 + 1] + bs[col + 1]);
                            *(__half2*)(crow + col) = v;
                        }
                    }
                }
        }
        __syncthreads();
    }
}

// ---------------- zero init ----------------
__global__ void zero_kernel() {
    int i = blockIdx.x * blockDim.x + threadIdx.x;
    if (i < NN) { g_srccnt[i] = 0; g_dstcnt[i] = 0; }
    if (i < D)  { g_bnsum[i] = 0.f; g_bnssum[i] = 0.f; }
}

// ---------------- BatchNorm: fast stats ----------------
__global__ __launch_bounds__(256) void bn_stats(const float* __restrict__ h) {
    __shared__ float4 shs[8][32], shss[8][32];
    int cq = threadIdx.x & 31;          // channel quad (4 channels)
    int rg = threadIdx.x >> 5;          // row subgroup 0..7
    float4 s = {0.f, 0.f, 0.f, 0.f}, ss = {0.f, 0.f, 0.f, 0.f};
    for (int r = blockIdx.x * 8 + rg; r < NN; r += gridDim.x * 8) {
        float4 v = *(const float4*)(h + (size_t)r * D + cq * 4);
        s.x += v.x; s.y += v.y; s.z += v.z; s.w += v.w;
        ss.x = fmaf(v.x, v.x, ss.x); ss.y = fmaf(v.y, v.y, ss.y);
        ss.z = fmaf(v.z, v.z, ss.z); ss.w = fmaf(v.w, v.w, ss.w);
    }
    shs[rg][cq] = s; shss[rg][cq] = ss;
    __syncthreads();
    if (rg == 0) {
#pragma unroll
        for (int i = 1; i < 8; i++) {
            float4 a = shs[i][cq], b = shss[i][cq];
            s.x += a.x; s.y += a.y; s.z += a.z; s.w += a.w;
            ss.x += b.x; ss.y += b.y; ss.z += b.z; ss.w += b.w;
        }
        atomicAdd(&g_bnsum[cq * 4 + 0], s.x);  atomicAdd(&g_bnsum[cq * 4 + 1], s.y);
        atomicAdd(&g_bnsum[cq * 4 + 2], s.z);  atomicAdd(&g_bnsum[cq * 4 + 3], s.w);
        atomicAdd(&g_bnssum[cq * 4 + 0], ss.x); atomicAdd(&g_bnssum[cq * 4 + 1], ss.y);
        atomicAdd(&g_bnssum[cq * 4 + 2], ss.z); atomicAdd(&g_bnssum[cq * 4 + 3], ss.w);
    }
}

__global__ __launch_bounds__(256) void bn_apply(const float* __restrict__ in, float* __restrict__ out,
                                                const float* __restrict__ g, const float* __restrict__ b) {
    int i = blockIdx.x * blockDim.x + threadIdx.x;
    if (i >= NN * 32) return;
    int cq = (i & 31) * 4;
    float4 v = *(const float4*)(in + (size_t)i * 4);
    float4 o;
#pragma unroll
    for (int j = 0; j < 4; j++) {
        int c = cq + j;
        float mu = g_bnsum[c] * (1.f / NN);
        float var = g_bnssum[c] * (1.f / NN) - mu * mu;
        float x = ((&v.x)[j] - mu) * rsqrtf(var + 1e-5f) * g[c] + b[c];
        (&o.x)[j] = fmaxf(x, 0.f);
    }
    *(float4*)(out + (size_t)i * 4) = o;
}

// ---------------- graph preprocessing ----------------
__global__ void count_edges(const int* __restrict__ ei, int E) {
    int e = blockIdx.x * blockDim.x + threadIdx.x;
    if (e >= E) return;
    atomicAdd(&g_dstcnt[ei[e]], 1);
    atomicAdd(&g_srccnt[ei[E + e]], 1);
}

__global__ void scan_local() {
    __shared__ int sh[1024];
    int b = blockIdx.x, tid = threadIdx.x;
    int i = b * 1024 + tid;
    int v = (i < NN) ? g_dstcnt[i] : 0;
    sh[tid] = v;
    __syncthreads();
    for (int o = 1; o < 1024; o <<= 1) {
        int x = (tid >= o) ? sh[tid - o] : 0;
        __syncthreads();
        sh[tid] += x;
        __syncthreads();
    }
    if (i < NN) g_scanloc[i] = sh[tid];
    if (tid == 1023) g_bsum[b] = sh[1023];
}
__global__ void scan_bsum() {
    int tid = threadIdx.x;
    if (tid == 0) {
        int run = 0;
        for (int b = 0; b < NB; b++) { g_boff[b] = run; run += g_bsum[b]; }
        g_rowoff[NN] = run;
    }
}
__global__ void scan_add() {       // also computes dis
    int i = blockIdx.x * blockDim.x + threadIdx.x;
    if (i >= NN) return;
    int ex = g_boff[i >> 10] + g_scanloc[i] - g_dstcnt[i];
    g_rowoff[i] = ex;
    g_cursor[i] = ex;
    int d = g_srccnt[i];
    g_dis[i] = (d > 0) ? rsqrtf((float)d) : 0.f;
}

__global__ void scatter_kernel(const int* __restrict__ ei, const int* __restrict__ ety, int E) {
    int e = blockIdx.x * blockDim.x + threadIdx.x;
    if (e >= E) return;
    int dst = ei[e];
    int src = ei[E + e];
    int r = ety[e];
    int pos = atomicAdd(&g_cursor[dst], 1);
    g_pack[pos] = src | (r << 16);
    g_norm[pos] = g_dis[dst] * g_dis[src];
}

// ---------------- edge aggregation: warp per dst node, 2-edge unroll ----------------
__global__ __launch_bounds__(256) void aggregate(
    const float* __restrict__ xlin, const __half* __restrict__ yh, float* __restrict__ z)
{
    int w = (blockIdx.x * blockDim.x + threadIdx.x) >> 5;
    int lane = threadIdx.x & 31;
    if (w >= NN) return;
    int beg = g_rowoff[w], end = g_rowoff[w + 1];

    float4 gz = {0.f, 0.f, 0.f, 0.f};
    float4 sz = {0.f, 0.f, 0.f, 0.f};
    float4 tz = {0.f, 0.f, 0.f, 0.f};

    int e = beg;
    for (; e + 2 <= end; e += 2) {
        int pk0 = g_pack[e], pk1 = g_pack[e + 1];
        float nm0 = g_norm[e], nm1 = g_norm[e + 1];
        int s0 = pk0 & 0xFFFF, r0 = pk0 >> 16;
        int s1 = pk1 & 0xFFFF, r1 = pk1 >> 16;
        float4 xv0 = *(const float4*)(xlin + (size_t)s0 * D + lane * 4);
        uint2  yp0 = *(const uint2*)(yh + ((size_t)r0 * NN + (size_t)s0) * D + lane * 4);
        float4 xv1 = *(const float4*)(xlin + (size_t)s1 * D + lane * 4);
        uint2  yp1 = *(const uint2*)(yh + ((size_t)r1 * NN + (size_t)s1) * D + lane * 4);

        float2 a0 = __half22float2(*(__half2*)&yp0.x);
        float2 a1 = __half22float2(*(__half2*)&yp0.y);
        gz.x = fmaf(xv0.x, nm0, gz.x); gz.y = fmaf(xv0.y, nm0, gz.y);
        gz.z = fmaf(xv0.z, nm0, gz.z); gz.w = fmaf(xv0.w, nm0, gz.w);
        float e0 = __expf(a0.x), e1 = __expf(a0.y), e2 = __expf(a1.x), e3 = __expf(a1.y);
        sz.x += e0; sz.y += e1; sz.z += e2; sz.w += e3;
        tz.x = fmaf(a0.x, e0, tz.x); tz.y = fmaf(a0.y, e1, tz.y);
        tz.z = fmaf(a1.x, e2, tz.z); tz.w = fmaf(a1.y, e3, tz.w);

        float2 b0 = __half22float2(*(__half2*)&yp1.x);
        float2 b1 = __half22float2(*(__half2*)&yp1.y);
        gz.x = fmaf(xv1.x, nm1, gz.x); gz.y = fmaf(xv1.y, nm1, gz.y);
        gz.z = fmaf(xv1.z, nm1, gz.z); gz.w = fmaf(xv1.w, nm1, gz.w);
        float f0 = __expf(b0.x), f1 = __expf(b0.y), f2 = __expf(b1.x), f3 = __expf(b1.y);
        sz.x += f0; sz.y += f1; sz.z += f2; sz.w += f3;
        tz.x = fmaf(b0.x, f0, tz.x); tz.y = fmaf(b0.y, f1, tz.y);
        tz.z = fmaf(b1.x, f2, tz.z); tz.w = fmaf(b1.y, f3, tz.w);
    }
    if (e < end) {
        int pk = g_pack[e];
        float nm = g_norm[e];
        int src = pk & 0xFFFF, r = pk >> 16;
        float4 xv = *(const float4*)(xlin + (size_t)src * D + lane * 4);
        uint2 yp = *(const uint2*)(yh + ((size_t)r * NN + (size_t)src) * D + lane * 4);
        float2 y0 = __half22float2(*(__half2*)&yp.x);
        float2 y1 = __half22float2(*(__half2*)&yp.y);
        gz.x = fmaf(xv.x, nm, gz.x); gz.y = fmaf(xv.y, nm, gz.y);
        gz.z = fmaf(xv.z, nm, gz.z); gz.w = fmaf(xv.w, nm, gz.w);
        float e0 = __expf(y0.x), e1 = __expf(y0.y), e2 = __expf(y1.x), e3 = __expf(y1.y);
        sz.x += e0; sz.y += e1; sz.z += e2; sz.w += e3;
        tz.x = fmaf(y0.x, e0, tz.x); tz.y = fmaf(y0.y, e1, tz.y);
        tz.z = fmaf(y1.x, e2, tz.z); tz.w = fmaf(y1.y, e3, tz.w);
    }

    float4 o;
    if (end > beg) {
        o.x = gz.x + 0.1f * fmaxf(tz.x / sz.x, 0.f);
        o.y = gz.y + 0.1f * fmaxf(tz.y / sz.y, 0.f);
        o.z = gz.z + 0.1f * fmaxf(tz.z / sz.z, 0.f);
        o.w = gz.w + 0.1f * fmaxf(tz.w / sz.w, 0.f);
    } else {
        o = gz;
    }
    *(float4*)(z + (size_t)w * D + lane * 4) = o;
}

// ---------------- final gather + exact GELU ----------------
__global__ void gather_gelu(const float* __restrict__ h, const int* __restrict__ idx,
                            float* __restrict__ out, int NI) {
    int i = blockIdx.x * blockDim.x + threadIdx.x;
    if (i >= NI * D) return;
    int row = idx[i >> 7];
    float v = h[(size_t)row * D + (i & (D - 1))];
    out[i] = 0.5f * v * (1.0f + erff(v * 0.70710678118654752f));
}

// ---------------- launch ----------------
extern "C" void kernel_launch(void* const* d_in, const int* in_sizes, int n_in,
                              void* d_out, int out_size) {
    const float* x      = (const float*)d_in[0];
    const int*   ei     = (const int*)d_in[1];
    const int*   ety    = (const int*)d_in[2];
    const int*   idx    = (const int*)d_in[4];
    const float* proj_w = (const float*)d_in[5];
    const float* proj_b = (const float*)d_in[6];
    const float* bn_g   = (const float*)d_in[7];
    const float* bn_b   = (const float*)d_in[8];
    const float* win_w[2]  = { (const float*)d_in[9],  (const float*)d_in[14] };
    const float* win_b[2]  = { (const float*)d_in[10], (const float*)d_in[15] };
    const float* wrel[2]   = { (const float*)d_in[11], (const float*)d_in[16] };
    const float* cout_w[2] = { (const float*)d_in[12], (const float*)d_in[17] };
    const float* cout_b[2] = { (const float*)d_in[13], (const float*)d_in[18] };

    const int E  = in_sizes[1] / 2;
    const int NI = in_sizes[4];
    float* out = (float*)d_out;

    float *buf0, *buf1, *xlin, *z, *ybias;
    __half* yh;
    unsigned char* wbuf;
    cudaGetSymbolAddress((void**)&buf0, g_buf0);
    cudaGetSymbolAddress((void**)&buf1, g_buf1);
    cudaGetSymbolAddress((void**)&xlin, g_xlin);
    cudaGetSymbolAddress((void**)&yh,   g_yh);
    cudaGetSymbolAddress((void**)&z,    g_z);
    cudaGetSymbolAddress((void**)&wbuf, g_w);
    cudaGetSymbolAddress((void**)&ybias, g_ybias);

    cudaFuncSetAttribute(gemm_mma, cudaFuncAttributeMaxDynamicSharedMemorySize, SM_TOTAL);
    cudaFuncSetAttribute(gemm6, cudaFuncAttributeMaxDynamicSharedMemorySize, SM6_TOTAL);
    cudaFuncSetAttribute(prep_all, cudaFuncAttributeMaxDynamicSharedMemorySize, 65536);

    const int GB = (NN + 127) / 128;

    zero_kernel<<<(NN + 255) / 256, 256>>>();
    prep_all<<<NMAT, 256, 65536>>>(proj_w, win_w[0], wrel[0], cout_w[0],
                                   win_w[1], wrel[1], cout_w[1], win_b[0], win_b[1]);

    gemm_mma<<<GB, 256, SM_TOTAL>>>(x, wbuf, proj_b, buf0, NN);
    bn_stats<<<512, 256>>>(buf0);
    bn_apply<<<(NN * 32 + 255) / 256, 256>>>(buf0, buf1, bn_g, bn_b);

    count_edges<<<(E + 511) / 512, 512>>>(ei, E);
    scan_local<<<NB, 1024>>>();
    scan_bsum<<<1, 32>>>();
    scan_add<<<(NN + 1023) / 1024, 1024>>>();
    scatter_kernel<<<(E + 511) / 512, 512>>>(ei, ety, E);

    const float* hin = buf1;
    float* hout = buf0;
    for (int L = 0; L < 2; L++) {
        gemm6<<<GB, 256, SM6_TOTAL>>>(hin, wbuf + (size_t)(1 + L * 7) * WBYTES, win_b[L],
                                      ybias + (size_t)L * RELS * D, xlin, yh, NN);
        aggregate<<<(NN * 32 + 255) / 256, 256>>>(xlin, yh, z);
        gemm_mma<<<GB, 256, SM_TOTAL>>>(z, wbuf + (size_t)(7 + L * 7) * WBYTES, cout_b[L], hout, NN);
        float* t = (float*)hin; hin = hout; hout = t;
    }

    gather_gelu<<<(NI * D + 255) / 256, 256>>>(hin, idx, out, NI);
}

// round 6
// speedup vs baseline: 1.3575x; 1.0174x over previous
#include <cuda_runtime.h>
#include <cuda_bf16.h>
#include <cuda_fp16.h>
#include <math.h>
#include <stdint.h>

#define NN 48758
#define EE 750000
#define D 128
#define RELS 5
#define NMAT 15
#define PADK 136
#define WBYTES 69632
#define NB 48

// ---------------- static device scratch ----------------
__device__ __align__(256) float g_buf0[NN * D];
__device__ __align__(256) float g_buf1[NN * D];
__device__ __align__(256) __half g_x16[NN * D];
__device__ __align__(256) __half g_yh[(size_t)RELS * NN * D];   // node-major [node][rel][ch]
__device__ __align__(256) float g_z[NN * D];
__device__ float g_bnsum[D];
__device__ float g_bnssum[D];
__device__ float g_bnscale[D];
__device__ float g_bnshift[D];
__device__ int   g_srccnt[NN];
__device__ int   g_dstcnt[NN];
__device__ float g_dis[NN];
__device__ int   g_rowoff[NN + 1];
__device__ int   g_cursor[NN];
__device__ int   g_scanloc[NN];
__device__ int   g_bsum[NB];
__device__ int   g_boff[NB];
__device__ int2  g_edge[EE];
__device__ __align__(256) unsigned char g_w[(size_t)NMAT * WBYTES];
__device__ float g_ybias[2 * RELS * D];

// ---------------- helpers ----------------
__device__ __forceinline__ uint32_t smem_u32(const void* p) {
    uint32_t a;
    asm("{ .reg .u64 t; cvta.to.shared.u64 t, %1; cvt.u32.u64 %0, t; }" : "=r"(a) : "l"(p));
    return a;
}
__device__ __forceinline__ uint32_t pack_bf2(__nv_bfloat16 lo, __nv_bfloat16 hi) {
    return ((uint32_t)__bfloat16_as_ushort(hi) << 16) | (uint32_t)__bfloat16_as_ushort(lo);
}
__device__ __forceinline__ void split_pair(float x0, float x1, uint32_t& hi2, uint32_t& lo2) {
    __nv_bfloat16 h0 = __float2bfloat16(x0), h1 = __float2bfloat16(x1);
    __nv_bfloat16 l0 = __float2bfloat16(x0 - __bfloat162float(h0));
    __nv_bfloat16 l1 = __float2bfloat16(x1 - __bfloat162float(h1));
    hi2 = pack_bf2(h0, h1);
    lo2 = pack_bf2(l0, l1);
}
__device__ __forceinline__ void ldmx4(uint32_t* r, uint32_t addr) {
    asm volatile("ldmatrix.sync.aligned.m8n8.x4.shared.b16 {%0,%1,%2,%3}, [%4];"
                 : "=r"(r[0]), "=r"(r[1]), "=r"(r[2]), "=r"(r[3]) : "r"(addr));
}
__device__ __forceinline__ void ldmx4t(uint32_t* r, uint32_t addr) {
    asm volatile("ldmatrix.sync.aligned.m8n8.x4.trans.shared.b16 {%0,%1,%2,%3}, [%4];"
                 : "=r"(r[0]), "=r"(r[1]), "=r"(r[2]), "=r"(r[3]) : "r"(addr));
}
__device__ __forceinline__ void mma16816(float* c, const uint32_t* a, const uint32_t* b) {
    asm volatile(
        "mma.sync.aligned.m16n8k16.row.col.f32.bf16.bf16.f32 "
        "{%0,%1,%2,%3}, {%4,%5,%6,%7}, {%8,%9}, {%0,%1,%2,%3};"
        : "+f"(c[0]), "+f"(c[1]), "+f"(c[2]), "+f"(c[3])
        : "r"(a[0]), "r"(a[1]), "r"(a[2]), "r"(a[3]), "r"(b[0]), "r"(b[1]));
}
__device__ __forceinline__ void cpasync16(uint32_t sdst, const void* gsrc) {
    asm volatile("cp.async.cg.shared.global [%0], [%1], 16;" :: "r"(sdst), "l"(gsrc) : "memory");
}
__device__ __forceinline__ void cp_commit() {
    asm volatile("cp.async.commit_group;" ::: "memory");
}

// ---------------- merged prep ----------------
__device__ void split_direct(const float* __restrict__ W, unsigned char* dst) {
    for (int idx = threadIdx.x; idx < 128 * 64; idx += blockDim.x) {
        int k = idx >> 6, n = (idx & 63) * 2;
        uint32_t hi2, lo2;
        split_pair(W[k * 128 + n], W[k * 128 + n + 1], hi2, lo2);
        *(uint32_t*)(dst + (size_t)(k * PADK + n) * 2) = hi2;
        *(uint32_t*)(dst + 34816 + (size_t)(k * PADK + n) * 2) = lo2;
    }
}

__global__ void prep_all(
    const float* __restrict__ proj,
    const float* __restrict__ win0, const float* __restrict__ wrel0,
    const float* __restrict__ cout0,
    const float* __restrict__ win1, const float* __restrict__ wrel1,
    const float* __restrict__ cout1,
    const float* __restrict__ win0b, const float* __restrict__ win1b)
{
    extern __shared__ float ws[];
    int b = blockIdx.x, tid = threadIdx.x;

    if (b == 0)  { split_direct(proj,  g_w + 0 * (size_t)WBYTES);  return; }
    if (b == 1)  { split_direct(win0,  g_w + 1 * (size_t)WBYTES);  return; }
    if (b == 7)  { split_direct(cout0, g_w + 7 * (size_t)WBYTES);  return; }
    if (b == 8)  { split_direct(win1,  g_w + 8 * (size_t)WBYTES);  return; }
    if (b == 14) { split_direct(cout1, g_w + 14 * (size_t)WBYTES); return; }

    int L = (b >= 9) ? 1 : 0;
    int r = L ? (b - 9) : (b - 2);
    const float* win = L ? win1 : win0;
    const float* wrl = (L ? wrel1 : wrel0) + (size_t)r * 16384;
    const float* wb  = L ? win1b : win0b;
    unsigned char* dst = g_w + (size_t)b * WBYTES;

    for (int i = tid; i < 4096; i += blockDim.x)
        ((float4*)ws)[i] = ((const float4*)wrl)[i];
    __syncthreads();

    int n = tid & 127;
    int kbase = (tid >> 7) * 64;
    for (int ko = 0; ko < 64; ko++) {
        int k = kbase + ko;
        const float* wr = win + (size_t)k * 128;
        float acc = 0.f;
#pragma unroll 8
        for (int j = 0; j < 128; j++) acc = fmaf(wr[j], ws[j * 128 + n], acc);
        __nv_bfloat16 h = __float2bfloat16(acc);
        __nv_bfloat16 l = __float2bfloat16(acc - __bfloat162float(h));
        *(unsigned short*)(dst + (size_t)(k * PADK + n) * 2) = __bfloat16_as_ushort(h);
        *(unsigned short*)(dst + 34816 + (size_t)(k * PADK + n) * 2) = __bfloat16_as_ushort(l);
    }
    if (tid < 128) {
        float acc = 0.f;
#pragma unroll 8
        for (int k = 0; k < 128; k++) acc = fmaf(wb[k], ws[k * 128 + tid], acc);
        g_ybias[(L * RELS + r) * D + tid] = acc;
    }
}

// ---------------- mma compute core ----------------
__device__ __forceinline__ void mma_compute(
    const char* Abase, const char* Bbase, float acc[2][8][4], int wm, int wn, int lane)
{
#pragma unroll
    for (int mt = 0; mt < 2; mt++)
#pragma unroll
        for (int nt = 0; nt < 8; nt++)
#pragma unroll
            for (int i = 0; i < 4; i++) acc[mt][nt][i] = 0.f;

    const int arow = (lane & 15);
    const int acolb = (lane >> 4) * 8;

#pragma unroll
    for (int cb = 0; cb < 3; cb++) {
        const char* As = Abase + (cb == 2 ? 34816 : 0);
        const char* Bs = Bbase + (cb == 1 ? 34816 : 0);
#pragma unroll
        for (int k16 = 0; k16 < 8; k16++) {
            int k0 = k16 * 16;
            uint32_t afrag[2][4];
#pragma unroll
            for (int mt = 0; mt < 2; mt++) {
                int rr = wm * 32 + mt * 16 + arow;
                ldmx4(afrag[mt], smem_u32(As + (size_t)(rr * PADK + k0 + acolb) * 2));
            }
            uint32_t bfrag[8][2];
#pragma unroll
            for (int nt2 = 0; nt2 < 4; nt2++) {
                int rr = k0 + arow;
                int c = wn * 64 + nt2 * 16 + acolb;
                uint32_t t[4];
                ldmx4t(t, smem_u32(Bs + (size_t)(rr * PADK + c) * 2));
                bfrag[nt2 * 2][0] = t[0]; bfrag[nt2 * 2][1] = t[1];
                bfrag[nt2 * 2 + 1][0] = t[2]; bfrag[nt2 * 2 + 1][1] = t[3];
            }
#pragma unroll
            for (int mt = 0; mt < 2; mt++)
#pragma unroll
                for (int nt = 0; nt < 8; nt++)
                    mma16816(acc[mt][nt], afrag[mt], bfrag[nt]);
        }
    }
}

__device__ __forceinline__ void stage_A(char* smem, const float* __restrict__ A,
                                        int rowBase, int M, int aoff, int bnflag) {
    for (int idx = threadIdx.x; idx < 128 * 64; idx += 256) {
        int row = idx >> 6, k = (idx & 63) * 2;
        int gr = rowBase + row; if (gr >= M) gr = M - 1;
        float2 a = *(const float2*)(A + (size_t)gr * D + k);
        if (bnflag) {
            a.x = fmaxf(fmaf(a.x, g_bnscale[k], g_bnshift[k]), 0.f);
            a.y = fmaxf(fmaf(a.y, g_bnscale[k + 1], g_bnshift[k + 1]), 0.f);
        }
        uint32_t hi2, lo2;
        split_pair(a.x, a.y, hi2, lo2);
        *(uint32_t*)(smem + aoff + (size_t)(row * PADK + k) * 2) = hi2;
        *(uint32_t*)(smem + aoff + 34816 + (size_t)(row * PADK + k) * 2) = lo2;
    }
}

// ---------------- single GEMM (cout): C = A @ W + bias ----------------
#define SM_AHI  0
#define SM_BHI  69632
#define SM_BIAS 139264
#define SM_TOTAL 139776

__global__ __launch_bounds__(256, 1) void gemm_mma(
    const float* __restrict__ A, const unsigned char* __restrict__ Wp,
    const float* __restrict__ bias, float* __restrict__ C, int M)
{
    extern __shared__ char smem[];
    int tid = threadIdx.x, wid = tid >> 5, lane = tid & 31;
    int wm = wid & 3, wn = wid >> 2;
    int rowBase = blockIdx.x * 128;

    for (int i = tid; i < WBYTES / 16; i += 256)
        ((float4*)(smem + SM_BHI))[i] = ((const float4*)Wp)[i];
    if (tid < 128) ((float*)(smem + SM_BIAS))[tid] = bias[tid];
    stage_A(smem, A, rowBase, M, SM_AHI, 0);
    __syncthreads();

    float acc[2][8][4];
    mma_compute(smem + SM_AHI, smem + SM_BHI, acc, wm, wn, lane);

    const float* bs = (const float*)(smem + SM_BIAS);
    int r0 = rowBase + wm * 32 + (lane >> 2);
    int cb0 = wn * 64 + (lane & 3) * 2;
#pragma unroll
    for (int mt = 0; mt < 2; mt++)
#pragma unroll
        for (int half = 0; half < 2; half++) {
            int row = r0 + mt * 16 + half * 8;
            if (row < M) {
                float* crow = C + (size_t)row * D;
#pragma unroll
                for (int nt = 0; nt < 8; nt++) {
                    int col = cb0 + nt * 8;
                    float2 v = { acc[mt][nt][half * 2] + bs[col],
                                 acc[mt][nt][half * 2 + 1] + bs[col + 1] };
                    *(float2*)(crow + col) = v;
                }
            }
        }
}

// ---------------- proj GEMM with fused BN-stats ----------------
#define SMP_STAT  139776   // 128 sums + 128 sumsq = 1024B
#define SMP_TOTAL 140800

__global__ __launch_bounds__(256, 1) void gemm_proj(
    const float* __restrict__ A, const unsigned char* __restrict__ Wp,
    const float* __restrict__ bias, float* __restrict__ C, int M)
{
    extern __shared__ char smem[];
    int tid = threadIdx.x, wid = tid >> 5, lane = tid & 31;
    int wm = wid & 3, wn = wid >> 2;
    int rowBase = blockIdx.x * 128;

    float* ssum = (float*)(smem + SMP_STAT);
    float* ssq  = ssum + 128;
    if (tid < 128) { ssum[tid] = 0.f; ssq[tid] = 0.f; }

    for (int i = tid; i < WBYTES / 16; i += 256)
        ((float4*)(smem + SM_BHI))[i] = ((const float4*)Wp)[i];
    if (tid < 128) ((float*)(smem + SM_BIAS))[tid] = bias[tid];
    stage_A(smem, A, rowBase, M, SM_AHI, 0);
    __syncthreads();

    float acc[2][8][4];
    mma_compute(smem + SM_AHI, smem + SM_BHI, acc, wm, wn, lane);

    const float* bs = (const float*)(smem + SM_BIAS);
    int r0 = rowBase + wm * 32 + (lane >> 2);
    int cb0 = wn * 64 + (lane & 3) * 2;

    float cs[16], cq[16];
#pragma unroll
    for (int i = 0; i < 16; i++) { cs[i] = 0.f; cq[i] = 0.f; }

#pragma unroll
    for (int mt = 0; mt < 2; mt++)
#pragma unroll
        for (int half = 0; half < 2; half++) {
            int row = r0 + mt * 16 + half * 8;
            if (row < M) {
                float* crow = C + (size_t)row * D;
#pragma unroll
                for (int nt = 0; nt < 8; nt++) {
                    int col = cb0 + nt * 8;
                    float v0 = acc[mt][nt][half * 2] + bs[col];
                    float v1 = acc[mt][nt][half * 2 + 1] + bs[col + 1];
                    float2 v = { v0, v1 };
                    *(float2*)(crow + col) = v;
                    cs[nt * 2] += v0;      cq[nt * 2] = fmaf(v0, v0, cq[nt * 2]);
                    cs[nt * 2 + 1] += v1;  cq[nt * 2 + 1] = fmaf(v1, v1, cq[nt * 2 + 1]);
                }
            }
        }

#pragma unroll
    for (int nt = 0; nt < 8; nt++) {
        int col = cb0 + nt * 8;
        atomicAdd(&ssum[col], cs[nt * 2]);      atomicAdd(&ssq[col], cq[nt * 2]);
        atomicAdd(&ssum[col + 1], cs[nt * 2 + 1]); atomicAdd(&ssq[col + 1], cq[nt * 2 + 1]);
    }
    __syncthreads();
    if (tid < 128) {
        atomicAdd(&g_bnsum[tid], ssum[tid]);
        atomicAdd(&g_bnssum[tid], ssq[tid]);
    }
}

__global__ void bn_coef(const float* __restrict__ g, const float* __restrict__ b) {
    int c = threadIdx.x;
    float mu = g_bnsum[c] * (1.f / NN);
    float var = g_bnssum[c] * (1.f / NN) - mu * mu;
    float sc = g[c] * rsqrtf(var + 1e-5f);
    g_bnscale[c] = sc;
    g_bnshift[c] = b[c] - mu * sc;
}

// ---------------- A-stationary 6-matrix GEMM, fp16 outputs ----------------
#define SM6_A    0
#define SM6_B0   69632
#define SM6_B1   139264
#define SM6_BIAS 208896
#define SM6_TOTAL 212000

__global__ __launch_bounds__(256, 1) void gemm6(
    const float* __restrict__ A, const unsigned char* __restrict__ Wbase,
    const float* __restrict__ winb, const float* __restrict__ ybias,
    __half* __restrict__ x16, __half* __restrict__ yh, int M, int bnflag)
{
    extern __shared__ char smem[];
    uint32_t sb = smem_u32(smem);
    int tid = threadIdx.x, wid = tid >> 5, lane = tid & 31;
    int wm = wid & 3, wn = wid >> 2;
    int rowBase = blockIdx.x * 128;

    if (tid < 128) ((float*)(smem + SM6_BIAS))[tid] = winb[tid];
    for (int i = tid; i < RELS * 128; i += 256)
        ((float*)(smem + SM6_BIAS))[128 + i] = ybias[i];

    for (int i = tid; i < WBYTES / 16; i += 256)
        cpasync16(sb + SM6_B0 + i * 16, Wbase + (size_t)i * 16);
    cp_commit();

    stage_A(smem, A, rowBase, M, SM6_A, bnflag);

    int r0 = rowBase + wm * 32 + (lane >> 2);
    int cb0 = wn * 64 + (lane & 3) * 2;

#pragma unroll 1
    for (int z = 0; z < 6; z++) {
        int cur = z & 1;
        if (z < 5) {
            const unsigned char* Wn = Wbase + (size_t)(z + 1) * WBYTES;
            uint32_t bdst = sb + ((z + 1) & 1 ? SM6_B1 : SM6_B0);
            for (int i = tid; i < WBYTES / 16; i += 256)
                cpasync16(bdst + i * 16, Wn + (size_t)i * 16);
            cp_commit();
            asm volatile("cp.async.wait_group 1;" ::: "memory");
        } else {
            asm volatile("cp.async.wait_group 0;" ::: "memory");
        }
        __syncthreads();

        float acc[2][8][4];
        mma_compute(smem + SM6_A, smem + (cur ? SM6_B1 : SM6_B0), acc, wm, wn, lane);

        const float* bs = (const float*)(smem + SM6_BIAS) + z * 128;
#pragma unroll
        for (int mt = 0; mt < 2; mt++)
#pragma unroll
            for (int half = 0; half < 2; half++) {
                int row = r0 + mt * 16 + half * 8;
                if (row < M) {
                    __half* crow = (z == 0)
                        ? (x16 + (size_t)row * D)
                        : (yh + ((size_t)row * RELS + (z - 1)) * D);
#pragma unroll
                    for (int nt = 0; nt < 8; nt++) {
                        int col = cb0 + nt * 8;
                        __half2 v = __floats2half2_rn(acc[mt][nt][half * 2] + bs[col],
                                                      acc[mt][nt][half * 2 + 1] + bs[col + 1]);
                        *(__half2*)(crow + col) = v;
                    }
                }
            }
        __syncthreads();
    }
}

// ---------------- zero init ----------------
__global__ void zero_kernel() {
    int i = blockIdx.x * blockDim.x + threadIdx.x;
    if (i < NN) { g_srccnt[i] = 0; g_dstcnt[i] = 0; }
    if (i < D)  { g_bnsum[i] = 0.f; g_bnssum[i] = 0.f; }
}

// ---------------- graph preprocessing ----------------
__global__ void count_edges(const int* __restrict__ ei, int E) {
    int e = blockIdx.x * blockDim.x + threadIdx.x;
    if (e >= E) return;
    atomicAdd(&g_dstcnt[ei[e]], 1);
    atomicAdd(&g_srccnt[ei[E + e]], 1);
}

__global__ void scan_local() {
    __shared__ int sh[1024];
    int b = blockIdx.x, tid = threadIdx.x;
    int i = b * 1024 + tid;
    int v = (i < NN) ? g_dstcnt[i] : 0;
    sh[tid] = v;
    __syncthreads();
    for (int o = 1; o < 1024; o <<= 1) {
        int x = (tid >= o) ? sh[tid - o] : 0;
        __syncthreads();
        sh[tid] += x;
        __syncthreads();
    }
    if (i < NN) g_scanloc[i] = sh[tid];
    if (tid == 1023) g_bsum[b] = sh[1023];
}
__global__ void scan_bsum() {
    if (threadIdx.x == 0) {
        int run = 0;
        for (int b = 0; b < NB; b++) { g_boff[b] = run; run += g_bsum[b]; }
        g_rowoff[NN] = run;
    }
}
__global__ void scan_add() {
    int i = blockIdx.x * blockDim.x + threadIdx.x;
    if (i >= NN) return;
    int ex = g_boff[i >> 10] + g_scanloc[i] - g_dstcnt[i];
    g_rowoff[i] = ex;
    g_cursor[i] = ex;
    int d = g_srccnt[i];
    g_dis[i] = (d > 0) ? rsqrtf((float)d) : 0.f;
}

__global__ void scatter_kernel(const int* __restrict__ ei, const int* __restrict__ ety, int E) {
    int e = blockIdx.x * blockDim.x + threadIdx.x;
    if (e >= E) return;
    int dst = ei[e];
    int src = ei[E + e];
    int r = ety[e];
    int pos = atomicAdd(&g_cursor[dst], 1);
    int2 ed;
    ed.x = src | (r << 16);
    ed.y = __float_as_int(g_dis[dst] * g_dis[src]);
    g_edge[pos] = ed;
}

// ---------------- edge aggregation: warp per dst node, all-fp16 gathers ----------------
__global__ __launch_bounds__(256) void aggregate(
    const __half* __restrict__ x16, const __half* __restrict__ yh, float* __restrict__ z)
{
    int w = (blockIdx.x * blockDim.x + threadIdx.x) >> 5;
    int lane = threadIdx.x & 31;
    if (w >= NN) return;
    int beg = g_rowoff[w], end = g_rowoff[w + 1];

    float4 gz = {0.f, 0.f, 0.f, 0.f};
    float4 sz = {0.f, 0.f, 0.f, 0.f};
    float4 tz = {0.f, 0.f, 0.f, 0.f};

    int e = beg;
    for (; e + 2 <= end; e += 2) {
        int2 ed0 = g_edge[e], ed1 = g_edge[e + 1];
        int s0 = ed0.x & 0xFFFF, r0 = ed0.x >> 16;
        int s1 = ed1.x & 0xFFFF, r1 = ed1.x >> 16;
        float nm0 = __int_as_float(ed0.y), nm1 = __int_as_float(ed1.y);
        uint2 xp0 = *(const uint2*)(x16 + (size_t)s0 * D + lane * 4);
        uint2 yp0 = *(const uint2*)(yh + ((size_t)s0 * RELS + r0) * D + lane * 4);
        uint2 xp1 = *(const uint2*)(x16 + (size_t)s1 * D + lane * 4);
        uint2 yp1 = *(const uint2*)(yh + ((size_t)s1 * RELS + r1) * D + lane * 4);

        float2 x0a = __half22float2(*(__half2*)&xp0.x);
        float2 x0b = __half22float2(*(__half2*)&xp0.y);
        float2 a0 = __half22float2(*(__half2*)&yp0.x);
        float2 a1 = __half22float2(*(__half2*)&yp0.y);
        gz.x = fmaf(x0a.x, nm0, gz.x); gz.y = fmaf(x0a.y, nm0, gz.y);
        gz.z = fmaf(x0b.x, nm0, gz.z); gz.w = fmaf(x0b.y, nm0, gz.w);
        float e0 = __expf(a0.x), e1 = __expf(a0.y), e2 = __expf(a1.x), e3 = __expf(a1.y);
        sz.x += e0; sz.y += e1; sz.z += e2; sz.w += e3;
        tz.x = fmaf(a0.x, e0, tz.x); tz.y = fmaf(a0.y, e1, tz.y);
        tz.z = fmaf(a1.x, e2, tz.z); tz.w = fmaf(a1.y, e3, tz.w);

        float2 x1a = __half22float2(*(__half2*)&xp1.x);
        float2 x1b = __half22float2(*(__half2*)&xp1.y);
        float2 b0 = __half22float2(*(__half2*)&yp1.x);
        float2 b1 = __half22float2(*(__half2*)&yp1.y);
        gz.x = fmaf(x1a.x, nm1, gz.x); gz.y = fmaf(x1a.y, nm1, gz.y);
        gz.z = fmaf(x1b.x, nm1, gz.z); gz.w = fmaf(x1b.y, nm1, gz.w);
        float f0 = __expf(b0.x), f1 = __expf(b0.y), f2 = __expf(b1.x), f3 = __expf(b1.y);
        sz.x += f0; sz.y += f1; sz.z += f2; sz.w += f3;
        tz.x = fmaf(b0.x, f0, tz.x); tz.y = fmaf(b0.y, f1, tz.y);
        tz.z = fmaf(b1.x, f2, tz.z); tz.w = fmaf(b1.y, f3, tz.w);
    }
    if (e < end) {
        int2 ed = g_edge[e];
        int src = ed.x & 0xFFFF, r = ed.x >> 16;
        float nm = __int_as_float(ed.y);
        uint2 xp = *(const uint2*)(x16 + (size_t)src * D + lane * 4);
        uint2 yp = *(const uint2*)(yh + ((size_t)src * RELS + r) * D + lane * 4);
        float2 xa = __half22float2(*(__half2*)&xp.x);
        float2 xb = __half22float2(*(__half2*)&xp.y);
        float2 y0 = __half22float2(*(__half2*)&yp.x);
        float2 y1 = __half22float2(*(__half2*)&yp.y);
        gz.x = fmaf(xa.x, nm, gz.x); gz.y = fmaf(xa.y, nm, gz.y);
        gz.z = fmaf(xb.x, nm, gz.z); gz.w = fmaf(xb.y, nm, gz.w);
        float e0 = __expf(y0.x), e1 = __expf(y0.y), e2 = __expf(y1.x), e3 = __expf(y1.y);
        sz.x += e0; sz.y += e1; sz.z += e2; sz.w += e3;
        tz.x = fmaf(y0.x, e0, tz.x); tz.y = fmaf(y0.y, e1, tz.y);
        tz.z = fmaf(y1.x, e2, tz.z); tz.w = fmaf(y1.y, e3, tz.w);
    }

    float4 o;
    if (end > beg) {
        o.x = gz.x + 0.1f * fmaxf(tz.x / sz.x, 0.f);
        o.y = gz.y + 0.1f * fmaxf(tz.y / sz.y, 0.f);
        o.z = gz.z + 0.1f * fmaxf(tz.z / sz.z, 0.f);
        o.w = gz.w + 0.1f * fmaxf(tz.w / sz.w, 0.f);
    } else {
        o = gz;
    }
    *(float4*)(z + (size_t)w * D + lane * 4) = o;
}

// ---------------- final gather + exact GELU ----------------
__global__ void gather_gelu(const float* __restrict__ h, const int* __restrict__ idx,
                            float* __restrict__ out, int NI) {
    int i = blockIdx.x * blockDim.x + threadIdx.x;
    if (i >= NI * D) return;
    int row = idx[i >> 7];
    float v = h[(size_t)row * D + (i & (D - 1))];
    out[i] = 0.5f * v * (1.0f + erff(v * 0.70710678118654752f));
}

// ---------------- launch ----------------
extern "C" void kernel_launch(void* const* d_in, const int* in_sizes, int n_in,
                              void* d_out, int out_size) {
    const float* x      = (const float*)d_in[0];
    const int*   ei     = (const int*)d_in[1];
    const int*   ety    = (const int*)d_in[2];
    const int*   idx    = (const int*)d_in[4];
    const float* proj_w = (const float*)d_in[5];
    const float* proj_b = (const float*)d_in[6];
    const float* bn_g   = (const float*)d_in[7];
    const float* bn_b   = (const float*)d_in[8];
    const float* win_w[2]  = { (const float*)d_in[9],  (const float*)d_in[14] };
    const float* win_b[2]  = { (const float*)d_in[10], (const float*)d_in[15] };
    const float* wrel[2]   = { (const float*)d_in[11], (const float*)d_in[16] };
    const float* cout_w[2] = { (const float*)d_in[12], (const float*)d_in[17] };
    const float* cout_b[2] = { (const float*)d_in[13], (const float*)d_in[18] };

    const int E  = in_sizes[1] / 2;
    const int NI = in_sizes[4];
    float* out = (float*)d_out;

    float *buf0, *buf1, *z, *ybias;
    __half *x16, *yh;
    unsigned char* wbuf;
    cudaGetSymbolAddress((void**)&buf0, g_buf0);
    cudaGetSymbolAddress((void**)&buf1, g_buf1);
    cudaGetSymbolAddress((void**)&x16,  g_x16);
    cudaGetSymbolAddress((void**)&yh,   g_yh);
    cudaGetSymbolAddress((void**)&z,    g_z);
    cudaGetSymbolAddress((void**)&wbuf, g_w);
    cudaGetSymbolAddress((void**)&ybias, g_ybias);

    cudaFuncSetAttribute(gemm_mma, cudaFuncAttributeMaxDynamicSharedMemorySize, SM_TOTAL);
    cudaFuncSetAttribute(gemm_proj, cudaFuncAttributeMaxDynamicSharedMemorySize, SMP_TOTAL);
    cudaFuncSetAttribute(gemm6, cudaFuncAttributeMaxDynamicSharedMemorySize, SM6_TOTAL);
    cudaFuncSetAttribute(prep_all, cudaFuncAttributeMaxDynamicSharedMemorySize, 65536);

    const int GB = (NN + 127) / 128;

    zero_kernel<<<(NN + 255) / 256, 256>>>();
    prep_all<<<NMAT, 256, 65536>>>(proj_w, win_w[0], wrel[0], cout_w[0],
                                   win_w[1], wrel[1], cout_w[1], win_b[0], win_b[1]);

    // proj GEMM with fused BN-stats, then per-channel coefficients
    gemm_proj<<<GB, 256, SMP_TOTAL>>>(x, wbuf, proj_b, buf0, NN);
    bn_coef<<<1, 128>>>(bn_g, bn_b);

    // graph preprocessing
    count_edges<<<(E + 511) / 512, 512>>>(ei, E);
    scan_local<<<NB, 1024>>>();
    scan_bsum<<<1, 32>>>();
    scan_add<<<(NN + 1023) / 1024, 1024>>>();
    scatter_kernel<<<(E + 511) / 512, 512>>>(ei, ety, E);

    const float* hin = buf0;   // pre-BN h; BN applied inside gemm6 (bnflag=1)
    float* hout = buf1;
    for (int L = 0; L < 2; L++) {
        gemm6<<<GB, 256, SM6_TOTAL>>>(hin, wbuf + (size_t)(1 + L * 7) * WBYTES, win_b[L],
                                      ybias + (size_t)L * RELS * D, x16, yh, NN, L == 0 ? 1 : 0);
        aggregate<<<(NN * 32 + 255) / 256, 256>>>(x16, yh, z);
        gemm_mma<<<GB, 256, SM_TOTAL>>>(z, wbuf + (size_t)(7 + L * 7) * WBYTES, cout_b[L], hout, NN);
        float* t = (float*)hin; hin = hout; hout = t;
    }

    gather_gelu<<<(NI * D + 255) / 256, 256>>>(hin, idx, out, NI);
}

// round 7
// speedup vs baseline: 1.5239x; 1.1226x over previous
#include <cuda_runtime.h>
#include <cuda_bf16.h>
#include <cuda_fp16.h>
#include <math.h>
#include <stdint.h>

#define NN 48758
#define EE 750000
#define D 128
#define RELS 5
#define NMAT 15
#define PADK 136
#define WBYTES 69632
#define HBYTES 34816
#define NB 48

// ---------------- static device scratch ----------------
__device__ __align__(256) float g_buf0[NN * D];
__device__ __align__(256) float g_buf1[NN * D];
__device__ __align__(256) __half g_x16[NN * D];
__device__ __align__(256) __half g_yh[(size_t)RELS * NN * D];   // [node][rel][ch]
__device__ __align__(256) float g_z[NN * D];
__device__ float g_bnsum[D];
__device__ float g_bnssum[D];
__device__ int   g_srccnt[NN];
__device__ int   g_dstcnt[NN];
__device__ float g_dis[NN];
__device__ int   g_rowoff[NN + 1];
__device__ int   g_cursor[NN];
__device__ int   g_scanloc[NN];
__device__ int   g_bsum[NB];
__device__ int   g_boff[NB];
__device__ int2  g_edge[EE];
__device__ __align__(256) unsigned char g_w[(size_t)NMAT * WBYTES];
__device__ float g_ybias[2 * RELS * D];

// ---------------- helpers ----------------
__device__ __forceinline__ uint32_t smem_u32(const void* p) {
    uint32_t a;
    asm("{ .reg .u64 t; cvta.to.shared.u64 t, %1; cvt.u32.u64 %0, t; }" : "=r"(a) : "l"(p));
    return a;
}
__device__ __forceinline__ uint32_t pack_bf2(__nv_bfloat16 lo, __nv_bfloat16 hi) {
    return ((uint32_t)__bfloat16_as_ushort(hi) << 16) | (uint32_t)__bfloat16_as_ushort(lo);
}
__device__ __forceinline__ void split_pair(float x0, float x1, uint32_t& hi2, uint32_t& lo2) {
    __nv_bfloat16 h0 = __float2bfloat16(x0), h1 = __float2bfloat16(x1);
    __nv_bfloat16 l0 = __float2bfloat16(x0 - __bfloat162float(h0));
    __nv_bfloat16 l1 = __float2bfloat16(x1 - __bfloat162float(h1));
    hi2 = pack_bf2(h0, h1);
    lo2 = pack_bf2(l0, l1);
}
__device__ __forceinline__ void ldmx4(uint32_t* r, uint32_t addr) {
    asm volatile("ldmatrix.sync.aligned.m8n8.x4.shared.b16 {%0,%1,%2,%3}, [%4];"
                 : "=r"(r[0]), "=r"(r[1]), "=r"(r[2]), "=r"(r[3]) : "r"(addr));
}
__device__ __forceinline__ void ldmx4t(uint32_t* r, uint32_t addr) {
    asm volatile("ldmatrix.sync.aligned.m8n8.x4.trans.shared.b16 {%0,%1,%2,%3}, [%4];"
                 : "=r"(r[0]), "=r"(r[1]), "=r"(r[2]), "=r"(r[3]) : "r"(addr));
}
__device__ __forceinline__ void mma16816(float* c, const uint32_t* a, const uint32_t* b) {
    asm volatile(
        "mma.sync.aligned.m16n8k16.row.col.f32.bf16.bf16.f32 "
        "{%0,%1,%2,%3}, {%4,%5,%6,%7}, {%8,%9}, {%0,%1,%2,%3};"
        : "+f"(c[0]), "+f"(c[1]), "+f"(c[2]), "+f"(c[3])
        : "r"(a[0]), "r"(a[1]), "r"(a[2]), "r"(a[3]), "r"(b[0]), "r"(b[1]));
}
__device__ __forceinline__ void cpasync16(uint32_t sdst, const void* gsrc) {
    asm volatile("cp.async.cg.shared.global [%0], [%1], 16;" :: "r"(sdst), "l"(gsrc) : "memory");
}
__device__ __forceinline__ void cp_commit() {
    asm volatile("cp.async.commit_group;" ::: "memory");
}

// ---------------- merged prep ----------------
// slots: 0=proj(hi/lo), 1=win0(hi/lo), 2..6=comp0_r(hi only), 7=cout0(hi/lo),
//        8=win1(hi/lo), 9..13=comp1_r(hi only), 14=cout1(hi/lo)
__device__ void split_direct(const float* __restrict__ W, unsigned char* dst) {
    for (int idx = threadIdx.x; idx < 128 * 64; idx += blockDim.x) {
        int k = idx >> 6, n = (idx & 63) * 2;
        uint32_t hi2, lo2;
        split_pair(W[k * 128 + n], W[k * 128 + n + 1], hi2, lo2);
        *(uint32_t*)(dst + (size_t)(k * PADK + n) * 2) = hi2;
        *(uint32_t*)(dst + HBYTES + (size_t)(k * PADK + n) * 2) = lo2;
    }
}

__global__ void prep_all(
    const float* __restrict__ proj,
    const float* __restrict__ win0, const float* __restrict__ wrel0,
    const float* __restrict__ cout0,
    const float* __restrict__ win1, const float* __restrict__ wrel1,
    const float* __restrict__ cout1,
    const float* __restrict__ win0b, const float* __restrict__ win1b)
{
    extern __shared__ float ws[];
    int b = blockIdx.x, tid = threadIdx.x;

    if (b == 0)  { split_direct(proj,  g_w + 0 * (size_t)WBYTES);  return; }
    if (b == 1)  { split_direct(win0,  g_w + 1 * (size_t)WBYTES);  return; }
    if (b == 7)  { split_direct(cout0, g_w + 7 * (size_t)WBYTES);  return; }
    if (b == 8)  { split_direct(win1,  g_w + 8 * (size_t)WBYTES);  return; }
    if (b == 14) { split_direct(cout1, g_w + 14 * (size_t)WBYTES); return; }

    int L = (b >= 9) ? 1 : 0;
    int r = L ? (b - 9) : (b - 2);
    const float* win = L ? win1 : win0;
    const float* wrl = (L ? wrel1 : wrel0) + (size_t)r * 16384;
    const float* wb  = L ? win1b : win0b;
    unsigned char* dst = g_w + (size_t)b * WBYTES;

    for (int i = tid; i < 4096; i += blockDim.x)
        ((float4*)ws)[i] = ((const float4*)wrl)[i];
    __syncthreads();

    int n = tid & 127;
    int kbase = (tid >> 7) * 64;
    for (int ko = 0; ko < 64; ko++) {
        int k = kbase + ko;
        const float* wr = win + (size_t)k * 128;
        float acc = 0.f;
#pragma unroll 8
        for (int j = 0; j < 128; j++) acc = fmaf(wr[j], ws[j * 128 + n], acc);
        // composites: hi only (y-GEMMs use single-combo bf16)
        *(unsigned short*)(dst + (size_t)(k * PADK + n) * 2) =
            __bfloat16_as_ushort(__float2bfloat16(acc));
    }
    if (tid < 128) {
        float acc = 0.f;
#pragma unroll 8
        for (int k = 0; k < 128; k++) acc = fmaf(wb[k], ws[k * 128 + tid], acc);
        g_ybias[(L * RELS + r) * D + tid] = acc;
    }
}

// ---------------- mma compute core: NC combos ----------------
template<int NC>
__device__ __forceinline__ void mma_compute(
    const char* Abase, const char* Bbase, float acc[2][8][4], int wm, int wn, int lane)
{
#pragma unroll
    for (int mt = 0; mt < 2; mt++)
#pragma unroll
        for (int nt = 0; nt < 8; nt++)
#pragma unroll
            for (int i = 0; i < 4; i++) acc[mt][nt][i] = 0.f;

    const int arow = (lane & 15);
    const int acolb = (lane >> 4) * 8;

#pragma unroll
    for (int cb = 0; cb < NC; cb++) {
        const char* As = Abase + (cb == 2 ? HBYTES : 0);
        const char* Bs = Bbase + (cb == 1 ? HBYTES : 0);
#pragma unroll
        for (int k16 = 0; k16 < 8; k16++) {
            int k0 = k16 * 16;
            uint32_t afrag[2][4];
#pragma unroll
            for (int mt = 0; mt < 2; mt++) {
                int rr = wm * 32 + mt * 16 + arow;
                ldmx4(afrag[mt], smem_u32(As + (size_t)(rr * PADK + k0 + acolb) * 2));
            }
            uint32_t bfrag[8][2];
#pragma unroll
            for (int nt2 = 0; nt2 < 4; nt2++) {
                int rr = k0 + arow;
                int c = wn * 64 + nt2 * 16 + acolb;
                uint32_t t[4];
                ldmx4t(t, smem_u32(Bs + (size_t)(rr * PADK + c) * 2));
                bfrag[nt2 * 2][0] = t[0]; bfrag[nt2 * 2][1] = t[1];
                bfrag[nt2 * 2 + 1][0] = t[2]; bfrag[nt2 * 2 + 1][1] = t[3];
            }
#pragma unroll
            for (int mt = 0; mt < 2; mt++)
#pragma unroll
                for (int nt = 0; nt < 8; nt++)
                    mma16816(acc[mt][nt], afrag[mt], bfrag[nt]);
        }
    }
}

__device__ __forceinline__ void stage_A(char* smem, const float* __restrict__ A,
                                        int rowBase, int M, int aoff,
                                        const float* bnsc, const float* bnsh) {
    for (int idx = threadIdx.x; idx < 128 * 64; idx += 256) {
        int row = idx >> 6, k = (idx & 63) * 2;
        int gr = rowBase + row; if (gr >= M) gr = M - 1;
        float2 a = *(const float2*)(A + (size_t)gr * D + k);
        if (bnsc) {
            a.x = fmaxf(fmaf(a.x, bnsc[k], bnsh[k]), 0.f);
            a.y = fmaxf(fmaf(a.y, bnsc[k + 1], bnsh[k + 1]), 0.f);
        }
        uint32_t hi2, lo2;
        split_pair(a.x, a.y, hi2, lo2);
        *(uint32_t*)(smem + aoff + (size_t)(row * PADK + k) * 2) = hi2;
        *(uint32_t*)(smem + aoff + HBYTES + (size_t)(row * PADK + k) * 2) = lo2;
    }
}

// ---------------- single GEMM (cout): C = A @ W + bias ----------------
#define SM_AHI  0
#define SM_BHI  69632
#define SM_BIAS 139264
#define SM_TOTAL 139776

__global__ __launch_bounds__(256, 1) void gemm_mma(
    const float* __restrict__ A, const unsigned char* __restrict__ Wp,
    const float* __restrict__ bias, float* __restrict__ C, int M)
{
    extern __shared__ char smem[];
    int tid = threadIdx.x, wid = tid >> 5, lane = tid & 31;
    int wm = wid & 3, wn = wid >> 2;
    int rowBase = blockIdx.x * 128;

    for (int i = tid; i < WBYTES / 16; i += 256)
        ((float4*)(smem + SM_BHI))[i] = ((const float4*)Wp)[i];
    if (tid < 128) ((float*)(smem + SM_BIAS))[tid] = bias[tid];
    stage_A(smem, A, rowBase, M, SM_AHI, nullptr, nullptr);
    __syncthreads();

    float acc[2][8][4];
    mma_compute<3>(smem + SM_AHI, smem + SM_BHI, acc, wm, wn, lane);

    const float* bs = (const float*)(smem + SM_BIAS);
    int r0 = rowBase + wm * 32 + (lane >> 2);
    int cb0 = wn * 64 + (lane & 3) * 2;
#pragma unroll
    for (int mt = 0; mt < 2; mt++)
#pragma unroll
        for (int half = 0; half < 2; half++) {
            int row = r0 + mt * 16 + half * 8;
            if (row < M) {
                float* crow = C + (size_t)row * D;
#pragma unroll
                for (int nt = 0; nt < 8; nt++) {
                    int col = cb0 + nt * 8;
                    float2 v = { acc[mt][nt][half * 2] + bs[col],
                                 acc[mt][nt][half * 2 + 1] + bs[col + 1] };
                    *(float2*)(crow + col) = v;
                }
            }
        }
}

// ---------------- proj GEMM with fused BN-stats ----------------
#define SMP_STAT  139776
#define SMP_TOTAL 140800

__global__ __launch_bounds__(256, 1) void gemm_proj(
    const float* __restrict__ A, const unsigned char* __restrict__ Wp,
    const float* __restrict__ bias, float* __restrict__ C, int M)
{
    extern __shared__ char smem[];
    int tid = threadIdx.x, wid = tid >> 5, lane = tid & 31;
    int wm = wid & 3, wn = wid >> 2;
    int rowBase = blockIdx.x * 128;

    float* ssum = (float*)(smem + SMP_STAT);
    float* ssq  = ssum + 128;
    if (tid < 128) { ssum[tid] = 0.f; ssq[tid] = 0.f; }

    for (int i = tid; i < WBYTES / 16; i += 256)
        ((float4*)(smem + SM_BHI))[i] = ((const float4*)Wp)[i];
    if (tid < 128) ((float*)(smem + SM_BIAS))[tid] = bias[tid];
    stage_A(smem, A, rowBase, M, SM_AHI, nullptr, nullptr);
    __syncthreads();

    float acc[2][8][4];
    mma_compute<3>(smem + SM_AHI, smem + SM_BHI, acc, wm, wn, lane);

    const float* bs = (const float*)(smem + SM_BIAS);
    int r0 = rowBase + wm * 32 + (lane >> 2);
    int cb0 = wn * 64 + (lane & 3) * 2;

    float cs[16], cq[16];
#pragma unroll
    for (int i = 0; i < 16; i++) { cs[i] = 0.f; cq[i] = 0.f; }

#pragma unroll
    for (int mt = 0; mt < 2; mt++)
#pragma unroll
        for (int half = 0; half < 2; half++) {
            int row = r0 + mt * 16 + half * 8;
            if (row < M) {
                float* crow = C + (size_t)row * D;
#pragma unroll
                for (int nt = 0; nt < 8; nt++) {
                    int col = cb0 + nt * 8;
                    float v0 = acc[mt][nt][half * 2] + bs[col];
                    float v1 = acc[mt][nt][half * 2 + 1] + bs[col + 1];
                    float2 v = { v0, v1 };
                    *(float2*)(crow + col) = v;
                    cs[nt * 2] += v0;      cq[nt * 2] = fmaf(v0, v0, cq[nt * 2]);
                    cs[nt * 2 + 1] += v1;  cq[nt * 2 + 1] = fmaf(v1, v1, cq[nt * 2 + 1]);
                }
            }
        }

#pragma unroll
    for (int nt = 0; nt < 8; nt++) {
        int col = cb0 + nt * 8;
        atomicAdd(&ssum[col], cs[nt * 2]);      atomicAdd(&ssq[col], cq[nt * 2]);
        atomicAdd(&ssum[col + 1], cs[nt * 2 + 1]); atomicAdd(&ssq[col + 1], cq[nt * 2 + 1]);
    }
    __syncthreads();
    if (tid < 128) {
        atomicAdd(&g_bnsum[tid], ssum[tid]);
        atomicAdd(&g_bnssum[tid], ssq[tid]);
    }
}

// ---------------- A-stationary 6-matrix GEMM ----------------
// z=0: xlin = A@win (3-combo bf16, fp16 out); z=1..5: y_r = A@comp_r (1-combo bf16, fp16 out)
#define SM6_A    0
#define SM6_B0   69632
#define SM6_B1   139264
#define SM6_BIAS 208896
#define SM6_BN   211968
#define SM6_TOTAL 212992

__global__ __launch_bounds__(256, 1) void gemm6(
    const float* __restrict__ A, const unsigned char* __restrict__ Wbase,
    const float* __restrict__ winb, const float* __restrict__ ybias,
    const float* __restrict__ bn_g, const float* __restrict__ bn_b,
    __half* __restrict__ x16, __half* __restrict__ yh, int M, int bnflag)
{
    extern __shared__ char smem[];
    uint32_t sb = smem_u32(smem);
    int tid = threadIdx.x, wid = tid >> 5, lane = tid & 31;
    int wm = wid & 3, wn = wid >> 2;
    int rowBase = blockIdx.x * 128;

    float* bias = (float*)(smem + SM6_BIAS);
    float* bnsc = (float*)(smem + SM6_BN);
    float* bnsh = bnsc + 128;

    if (tid < 128) bias[tid] = winb[tid];
    for (int i = tid; i < RELS * 128; i += 256)
        bias[128 + i] = ybias[i];
    if (bnflag && tid < 128) {
        float mu = g_bnsum[tid] * (1.f / NN);
        float var = g_bnssum[tid] * (1.f / NN) - mu * mu;
        float sc = bn_g[tid] * rsqrtf(var + 1e-5f);
        bnsc[tid] = sc;
        bnsh[tid] = bn_b[tid] - mu * sc;
    }

    // g0: win hi/lo -> B0 ; g1: comp0 hi -> B1
    for (int i = tid; i < WBYTES / 16; i += 256)
        cpasync16(sb + SM6_B0 + i * 16, Wbase + (size_t)i * 16);
    cp_commit();
    {
        const unsigned char* c0 = Wbase + (size_t)WBYTES;
        for (int i = tid; i < HBYTES / 16; i += 256)
            cpasync16(sb + SM6_B1 + i * 16, c0 + (size_t)i * 16);
    }
    cp_commit();

    __syncthreads();   // bn coefs visible to all
    stage_A(smem, A, rowBase, M, SM6_A, bnflag ? bnsc : nullptr, bnflag ? bnsh : nullptr);

    int r0 = rowBase + wm * 32 + (lane >> 2);
    int cb0 = wn * 64 + (lane & 3) * 2;

#pragma unroll 1
    for (int z = 0; z < 6; z++) {
        // prefetch comp[z] (used at z+1) into the buffer freed by z-1
        if (z >= 1 && z <= 4) {
            const unsigned char* cz = Wbase + (size_t)(z + 1) * WBYTES;
            uint32_t bdst = sb + ((z & 1) ? SM6_B0 : SM6_B1);
            for (int i = tid; i < HBYTES / 16; i += 256)
                cpasync16(bdst + i * 16, cz + (size_t)i * 16);
            cp_commit();
        }
        if (z < 5) asm volatile("cp.async.wait_group 1;" ::: "memory");
        else       asm volatile("cp.async.wait_group 0;" ::: "memory");
        __syncthreads();

        const char* Bbuf = smem + ((z & 1) ? SM6_B1 : SM6_B0);
        float acc[2][8][4];
        if (z == 0) mma_compute<3>(smem + SM6_A, Bbuf, acc, wm, wn, lane);
        else        mma_compute<1>(smem + SM6_A, Bbuf, acc, wm, wn, lane);

        const float* bs = bias + z * 128;
#pragma unroll
        for (int mt = 0; mt < 2; mt++)
#pragma unroll
            for (int half = 0; half < 2; half++) {
                int row = r0 + mt * 16 + half * 8;
                if (row < M) {
                    __half* crow = (z == 0)
                        ? (x16 + (size_t)row * D)
                        : (yh + ((size_t)row * RELS + (z - 1)) * D);
#pragma unroll
                    for (int nt = 0; nt < 8; nt++) {
                        int col = cb0 + nt * 8;
                        __half2 v = __floats2half2_rn(acc[mt][nt][half * 2] + bs[col],
                                                      acc[mt][nt][half * 2 + 1] + bs[col + 1]);
                        *(__half2*)(crow + col) = v;
                    }
                }
            }
        __syncthreads();
    }
}

// ---------------- zero init ----------------
__global__ void zero_kernel() {
    int i = blockIdx.x * blockDim.x + threadIdx.x;
    if (i < NN) { g_srccnt[i] = 0; g_dstcnt[i] = 0; }
    if (i < D)  { g_bnsum[i] = 0.f; g_bnssum[i] = 0.f; }
}

// ---------------- graph preprocessing ----------------
__global__ void count_edges(const int* __restrict__ ei, int E) {
    int e = blockIdx.x * blockDim.x + threadIdx.x;
    if (e >= E) return;
    atomicAdd(&g_dstcnt[ei[e]], 1);
    atomicAdd(&g_srccnt[ei[E + e]], 1);
}

__global__ void scan_local() {
    __shared__ int sh[1024];
    int b = blockIdx.x, tid = threadIdx.x;
    int i = b * 1024 + tid;
    int v = (i < NN) ? g_dstcnt[i] : 0;
    sh[tid] = v;
    __syncthreads();
    for (int o = 1; o < 1024; o <<= 1) {
        int x = (tid >= o) ? sh[tid - o] : 0;
        __syncthreads();
        sh[tid] += x;
        __syncthreads();
    }
    if (i < NN) g_scanloc[i] = sh[tid];
    if (tid == 1023) g_bsum[b] = sh[1023];
}
__global__ void scan_bsum() {
    if (threadIdx.x == 0) {
        int run = 0;
        for (int b = 0; b < NB; b++) { g_boff[b] = run; run += g_bsum[b]; }
        g_rowoff[NN] = run;
    }
}
__global__ void scan_add() {
    int i = blockIdx.x * blockDim.x + threadIdx.x;
    if (i >= NN) return;
    int ex = g_boff[i >> 10] + g_scanloc[i] - g_dstcnt[i];
    g_rowoff[i] = ex;
    g_cursor[i] = ex;
    int d = g_srccnt[i];
    g_dis[i] = (d > 0) ? rsqrtf((float)d) : 0.f;
}

__global__ void scatter_kernel(const int* __restrict__ ei, const int* __restrict__ ety, int E) {
    int e = blockIdx.x * blockDim.x + threadIdx.x;
    if (e >= E) return;
    int dst = ei[e];
    int src = ei[E + e];
    int r = ety[e];
    int pos = atomicAdd(&g_cursor[dst], 1);
    int2 ed;
    ed.x = src | (r << 16);
    ed.y = __float_as_int(g_dis[dst] * g_dis[src]);
    g_edge[pos] = ed;
}

// ---------------- edge aggregation ----------------
__global__ __launch_bounds__(256) void aggregate(
    const __half* __restrict__ x16, const __half* __restrict__ yh, float* __restrict__ z)
{
    int w = (blockIdx.x * blockDim.x + threadIdx.x) >> 5;
    int lane = threadIdx.x & 31;
    if (w >= NN) return;
    int beg = g_rowoff[w], end = g_rowoff[w + 1];

    float4 gz = {0.f, 0.f, 0.f, 0.f};
    float4 sz = {0.f, 0.f, 0.f, 0.f};
    float4 tz = {0.f, 0.f, 0.f, 0.f};

    int e = beg;
    for (; e + 2 <= end; e += 2) {
        int2 ed0 = g_edge[e], ed1 = g_edge[e + 1];
        int s0 = ed0.x & 0xFFFF, r0 = ed0.x >> 16;
        int s1 = ed1.x & 0xFFFF, r1 = ed1.x >> 16;
        float nm0 = __int_as_float(ed0.y), nm1 = __int_as_float(ed1.y);
        uint2 xp0 = *(const uint2*)(x16 + (size_t)s0 * D + lane * 4);
        uint2 yp0 = *(const uint2*)(yh + ((size_t)s0 * RELS + r0) * D + lane * 4);
        uint2 xp1 = *(const uint2*)(x16 + (size_t)s1 * D + lane * 4);
        uint2 yp1 = *(const uint2*)(yh + ((size_t)s1 * RELS + r1) * D + lane * 4);

        float2 x0a = __half22float2(*(__half2*)&xp0.x);
        float2 x0b = __half22float2(*(__half2*)&xp0.y);
        float2 a0 = __half22float2(*(__half2*)&yp0.x);
        float2 a1 = __half22float2(*(__half2*)&yp0.y);
        gz.x = fmaf(x0a.x, nm0, gz.x); gz.y = fmaf(x0a.y, nm0, gz.y);
        gz.z = fmaf(x0b.x, nm0, gz.z); gz.w = fmaf(x0b.y, nm0, gz.w);
        float e0 = __expf(a0.x), e1 = __expf(a0.y), e2 = __expf(a1.x), e3 = __expf(a1.y);
        sz.x += e0; sz.y += e1; sz.z += e2; sz.w += e3;
        tz.x = fmaf(a0.x, e0, tz.x); tz.y = fmaf(a0.y, e1, tz.y);
        tz.z = fmaf(a1.x, e2, tz.z); tz.w = fmaf(a1.y, e3, tz.w);

        float2 x1a = __half22float2(*(__half2*)&xp1.x);
        float2 x1b = __half22float2(*(__half2*)&xp1.y);
        float2 b0 = __half22float2(*(__half2*)&yp1.x);
        float2 b1 = __half22float2(*(__half2*)&yp1.y);
        gz.x = fmaf(x1a.x, nm1, gz.x); gz.y = fmaf(x1a.y, nm1, gz.y);
        gz.z = fmaf(x1b.x, nm1, gz.z); gz.w = fmaf(x1b.y, nm1, gz.w);
        float f0 = __expf(b0.x), f1 = __expf(b0.y), f2 = __expf(b1.x), f3 = __expf(b1.y);
        sz.x += f0; sz.y += f1; sz.z += f2; sz.w += f3;
        tz.x = fmaf(b0.x, f0, tz.x); tz.y = fmaf(b0.y, f1, tz.y);
        tz.z = fmaf(b1.x, f2, tz.z); tz.w = fmaf(b1.y, f3, tz.w);
    }
    if (e < end) {
        int2 ed = g_edge[e];
        int src = ed.x & 0xFFFF, r = ed.x >> 16;
        float nm = __int_as_float(ed.y);
        uint2 xp = *(const uint2*)(x16 + (size_t)src * D + lane * 4);
        uint2 yp = *(const uint2*)(yh + ((size_t)src * RELS + r) * D + lane * 4);
        float2 xa = __half22float2(*(__half2*)&xp.x);
        float2 xb = __half22float2(*(__half2*)&xp.y);
        float2 y0 = __half22float2(*(__half2*)&yp.x);
        float2 y1 = __half22float2(*(__half2*)&yp.y);
        gz.x = fmaf(xa.x, nm, gz.x); gz.y = fmaf(xa.y, nm, gz.y);
        gz.z = fmaf(xb.x, nm, gz.z); gz.w = fmaf(xb.y, nm, gz.w);
        float e0 = __expf(y0.x), e1 = __expf(y0.y), e2 = __expf(y1.x), e3 = __expf(y1.y);
        sz.x += e0; sz.y += e1; sz.z += e2; sz.w += e3;
        tz.x = fmaf(y0.x, e0, tz.x); tz.y = fmaf(y0.y, e1, tz.y);
        tz.z = fmaf(y1.x, e2, tz.z); tz.w = fmaf(y1.y, e3, tz.w);
    }

    float4 o;
    if (end > beg) {
        o.x = gz.x + 0.1f * fmaxf(tz.x / sz.x, 0.f);
        o.y = gz.y + 0.1f * fmaxf(tz.y / sz.y, 0.f);
        o.z = gz.z + 0.1f * fmaxf(tz.z / sz.z, 0.f);
        o.w = gz.w + 0.1f * fmaxf(tz.w / sz.w, 0.f);
    } else {
        o = gz;
    }
    *(float4*)(z + (size_t)w * D + lane * 4) = o;
}

// ---------------- final gather + exact GELU ----------------
__global__ void gather_gelu(const float* __restrict__ h, const int* __restrict__ idx,
                            float* __restrict__ out, int NI) {
    int i = blockIdx.x * blockDim.x + threadIdx.x;
    if (i >= NI * D) return;
    int row = idx[i >> 7];
    float v = h[(size_t)row * D + (i & (D - 1))];
    out[i] = 0.5f * v * (1.0f + erff(v * 0.70710678118654752f));
}

// ---------------- launch ----------------
extern "C" void kernel_launch(void* const* d_in, const int* in_sizes, int n_in,
                              void* d_out, int out_size) {
    const float* x      = (const float*)d_in[0];
    const int*   ei     = (const int*)d_in[1];
    const int*   ety    = (const int*)d_in[2];
    const int*   idx    = (const int*)d_in[4];
    const float* proj_w = (const float*)d_in[5];
    const float* proj_b = (const float*)d_in[6];
    const float* bn_g   = (const float*)d_in[7];
    const float* bn_b   = (const float*)d_in[8];
    const float* win_w[2]  = { (const float*)d_in[9],  (const float*)d_in[14] };
    const float* win_b[2]  = { (const float*)d_in[10], (const float*)d_in[15] };
    const float* wrel[2]   = { (const float*)d_in[11], (const float*)d_in[16] };
    const float* cout_w[2] = { (const float*)d_in[12], (const float*)d_in[17] };
    const float* cout_b[2] = { (const float*)d_in[13], (const float*)d_in[18] };

    const int E  = in_sizes[1] / 2;
    const int NI = in_sizes[4];
    float* out = (float*)d_out;

    float *buf0, *buf1, *z, *ybias;
    __half *x16, *yh;
    unsigned char* wbuf;
    cudaGetSymbolAddress((void**)&buf0, g_buf0);
    cudaGetSymbolAddress((void**)&buf1, g_buf1);
    cudaGetSymbolAddress((void**)&x16,  g_x16);
    cudaGetSymbolAddress((void**)&yh,   g_yh);
    cudaGetSymbolAddress((void**)&z,    g_z);
    cudaGetSymbolAddress((void**)&wbuf, g_w);
    cudaGetSymbolAddress((void**)&ybias, g_ybias);

    cudaFuncSetAttribute(gemm_mma, cudaFuncAttributeMaxDynamicSharedMemorySize, SM_TOTAL);
    cudaFuncSetAttribute(gemm_proj, cudaFuncAttributeMaxDynamicSharedMemorySize, SMP_TOTAL);
    cudaFuncSetAttribute(gemm6, cudaFuncAttributeMaxDynamicSharedMemorySize, SM6_TOTAL);
    cudaFuncSetAttribute(prep_all, cudaFuncAttributeMaxDynamicSharedMemorySize, 65536);

    const int GB = (NN + 127) / 128;

    zero_kernel<<<(NN + 255) / 256, 256>>>();                              // 0
    prep_all<<<NMAT, 256, 65536>>>(proj_w, win_w[0], wrel[0], cout_w[0],   // 1
                                   win_w[1], wrel[1], cout_w[1], win_b[0], win_b[1]);
    gemm_proj<<<GB, 256, SMP_TOTAL>>>(x, wbuf, proj_b, buf0, NN);          // 2
    // layer-0 gemm6 at launch index 3 (profiled slot); BN fused via bnflag
    gemm6<<<GB, 256, SM6_TOTAL>>>(buf0, wbuf + (size_t)1 * WBYTES, win_b[0],   // 3
                                  ybias, bn_g, bn_b, x16, yh, NN, 1);

    count_edges<<<(E + 511) / 512, 512>>>(ei, E);
    scan_local<<<NB, 1024>>>();
    scan_bsum<<<1, 32>>>();
    scan_add<<<(NN + 1023) / 1024, 1024>>>();
    scatter_kernel<<<(E + 511) / 512, 512>>>(ei, ety, E);

    aggregate<<<(NN * 32 + 255) / 256, 256>>>(x16, yh, z);
    gemm_mma<<<GB, 256, SM_TOTAL>>>(z, wbuf + (size_t)7 * WBYTES, cout_b[0], buf1, NN);

    gemm6<<<GB, 256, SM6_TOTAL>>>(buf1, wbuf + (size_t)8 * WBYTES, win_b[1],
                                  ybias + RELS * D, bn_g, bn_b, x16, yh, NN, 0);
    aggregate<<<(NN * 32 + 255) / 256, 256>>>(x16, yh, z);
    gemm_mma<<<GB, 256, SM_TOTAL>>>(z, wbuf + (size_t)14 * WBYTES, cout_b[1], buf0, NN);

    gather_gelu<<<(NI * D + 255) / 256, 256>>>(buf0, idx, out, NI);
}